// round 15
// baseline (speedup 1.0000x reference)
#include <cuda_runtime.h>
#include <cuda_fp16.h>
#include <cstdint>

#define NN 50000
#define NE 600000
#define HH 128
#define LL 6

typedef unsigned long long u64;
typedef unsigned int u32;

// ---------------- scratch (static device buffers; no allocation) ----------------
__device__ float g_hn [NN*HH];      // raw pre-BN node tensor "n"
__device__ float g_up [NN*HH];
__device__ float g_agg[NN*HH];
__device__ float g_Pd [NN*HH];
__device__ float g_Ps [NN*HH];
__device__ float4 g_tl[NE];
__device__ int   g_sdst[NE];
__device__ int   g_ssrc[NE];
__device__ int   g_cnt[NN];
__device__ int   g_woff[NN];
__device__ int   g_bsum[128];
__device__ float g_invdeg[NN];
__device__ float g_var[NN];
__device__ float g_sum[HH];         // zero-init; every fin re-zeros (invariant)
__device__ float g_sumsq[HH];
__device__ float g_ba[HH];
__device__ float g_bc[HH];
__device__ int   g_tick;            // last-CTA ticket; zero-init; every fin re-zeros
#define NCHUNK_TOT 43
__device__ char g_Bimg[(size_t)NCHUNK_TOT * 65536];   // fp16 hi-limb [n][k], 32KB used/chunk

// ---------------- PTX helpers ----------------
__device__ __forceinline__ u32 smem_u32(const void* p){
    u32 a; asm("{ .reg .u64 t; cvta.to.shared.u64 t, %1; cvt.u32.u64 %0, t; }" : "=r"(a) : "l"(p));
    return a;
}
__device__ __forceinline__ void ldsm4(u32 &r0, u32 &r1, u32 &r2, u32 &r3, u32 addr){
    asm volatile("ldmatrix.sync.aligned.m8n8.x4.shared.b16 {%0,%1,%2,%3}, [%4];"
        : "=r"(r0), "=r"(r1), "=r"(r2), "=r"(r3) : "r"(addr));
}
__device__ __forceinline__ void mma16816(float4 &d, const u32* a, u32 b0, u32 b1){
    asm volatile("mma.sync.aligned.m16n8k16.row.col.f32.f16.f16.f32 "
        "{%0,%1,%2,%3}, {%4,%5,%6,%7}, {%8,%9}, {%0,%1,%2,%3};"
        : "+f"(d.x), "+f"(d.y), "+f"(d.z), "+f"(d.w)
        : "r"(a[0]), "r"(a[1]), "r"(a[2]), "r"(a[3]), "r"(b0), "r"(b1));
}
__device__ __forceinline__ u32 pack_h2(float v0, float v1){
    u32 r; asm("cvt.rn.f16x2.f32 %0, %1, %2;" : "=r"(r) : "f"(v1), "f"(v0)); return r;
}
__device__ __forceinline__ float trunc_hi(float v){
    return __uint_as_float(__float_as_uint(v) & 0xFFFFE000u);
}
__device__ __forceinline__ void split8(const float* v, u32* hw, u32* lw){
    #pragma unroll
    for (int q = 0; q < 4; q++){
        float h0 = trunc_hi(v[2*q]);
        float h1 = trunc_hi(v[2*q+1]);
        hw[q] = pack_h2(h0, h1);
        lw[q] = pack_h2(v[2*q] - h0, v[2*q+1] - h1);
    }
}

// BN fin: compute affine from stats, re-zero stats. Call with tid<128 active.
__device__ __forceinline__ void bn_fin_dev(int tid, const float* __restrict__ g,
                                           const float* __restrict__ be){
    if (tid < 128){
        float mu  = g_sum[tid]   * (1.f/NN);
        float var = g_sumsq[tid] * (1.f/NN) - mu*mu;
        float a = g[tid] * rsqrtf(var + 1e-5f);
        g_ba[tid] = a;
        g_bc[tid] = be[tid] - a*mu;
        g_sum[tid] = 0.f;
        g_sumsq[tid] = 0.f;
    }
}

#define EPI_RELU_STORE    0
#define EPI_SCATTER       1
#define EPI_RESID_STATS   2
#define EPI_STORE         3
#define EPI_STORE_STATS   4
#define EPI_RELU_STORE_V  5

// ======================================================================
// EDGE kernel (scatter GEMM), 2 CTAs/SM. R13 + interior-run plain stores.
// ======================================================================
struct FO {
    static constexpr int B0 = 40960;
    static constexpr int WT = B0 + 34816;
    static constexpr int I0 = WT + 2048;
    static constexpr int I1 = I0 + 512;
    static constexpr int TL = I1 + 512;
    static constexpr int BA = TL + 2048;
    static constexpr int BC = BA + 512;
    static constexpr int BI = BC + 512;
    static constexpr int TOT = BI + 512;
};

struct Pref1 { float4 x0, x1, y0, y1; };

__device__ __forceinline__ void edge_ldg(int i0, int i1, int kglob, Pref1& p){
    p.x0 = *(const float4*)&g_Pd[(size_t)i0*HH + kglob];
    p.x1 = *(const float4*)&g_Pd[(size_t)i0*HH + kglob + 4];
    p.y0 = *(const float4*)&g_Ps[(size_t)i1*HH + kglob];
    p.y1 = *(const float4*)&g_Ps[(size_t)i1*HH + kglob + 4];
}
__device__ __forceinline__ void edge_fin(const Pref1& p, int row, int kglob,
    const float* __restrict__ s_wt, const float4* __restrict__ s_tl, float* v)
{
    v[0]=p.x0.x+p.y0.x; v[1]=p.x0.y+p.y0.y; v[2]=p.x0.z+p.y0.z; v[3]=p.x0.w+p.y0.w;
    v[4]=p.x1.x+p.y1.x; v[5]=p.x1.y+p.y1.y; v[6]=p.x1.z+p.y1.z; v[7]=p.x1.w+p.y1.w;
    float4 tl = s_tl[row];
    #pragma unroll
    for (int t = 0; t < 4; t++){
        float tv = (&tl.x)[t];
        const float* wr = &s_wt[t*HH + kglob];
        #pragma unroll
        for (int kk = 0; kk < 8; kk++) v[kk] += tv * wr[kk];
    }
    #pragma unroll
    for (int kk = 0; kk < 8; kk++) v[kk] = fmaxf(v[kk], 0.f);
}

__device__ __forceinline__ void cvt_store(const float* v, char* smem, u32 aoff){
    u32 hw[4], lw[4];
    split8(v, hw, lw);
    *(uint4*)(smem + aoff)         = make_uint4(hw[0],hw[1],hw[2],hw[3]);
    *(uint4*)(smem + 10240 + aoff) = make_uint4(lw[0],lw[1],lw[2],lw[3]);
}

__global__ __launch_bounds__(256, 2)
void gemm_edge(const char* __restrict__ Bimg, const float* __restrict__ bias,
               float* __restrict__ out, const float* __restrict__ Wt, int rows)
{
    extern __shared__ __align__(16) char smem[];
    const u32 sb  = smem_u32(smem);
    const int tid = threadIdx.x;
    const int wid = tid >> 5;
    const int lane = tid & 31;

    int*    s_i0 = (int*)   (smem + FO::I0);
    int*    s_i1 = (int*)   (smem + FO::I1);
    float4* s_tl = (float4*)(smem + FO::TL);
    float*  s_bi = (float*) (smem + FO::BI);
    float*  s_wt = (float*) (smem + FO::WT);
    __shared__ int s_nh;
    __shared__ int s_hd[64];

    {
        const uint4* bsrc = (const uint4*)Bimg;
        for (int i = tid; i < 2048; i += 256){
            int row = i >> 4, cc = i & 15;
            *(uint4*)(smem + FO::B0 + row*272 + cc*16) = bsrc[i];
        }
    }
    for (int i = tid; i < 4*HH; i += 256) s_wt[i] = Wt[i];
    if (tid < 128) s_bi[tid] = bias[tid];

    const int warp_m = wid & 3;
    const int warp_n = wid >> 2;
    const int qi = lane & 7, qd = lane >> 3;
    const u32 a_rd = (u32)((warp_m*32 + (qd&1)*8 + qi)*80 + (qd>>1)*16);
    const u32 b_rd = sb + FO::B0 + (u32)((warp_n*64 + (qd>>1)*8 + qi)*272 + (qd&1)*16);

    for (int base = blockIdx.x * 128; base < rows; base += gridDim.x * 128){
        __syncthreads();
        if (tid < 128){
            int r = base + tid;
            bool v = r < rows;
            s_i0[tid] = v ? g_sdst[r] : 0;
            s_i1[tid] = v ? g_ssrc[r] : 0;
            s_tl[tid] = v ? g_tl[r]   : make_float4(0.f,0.f,0.f,0.f);
        }
        __syncthreads();

        float4 acc[2][8];
        #pragma unroll
        for (int i=0;i<2;i++)
            #pragma unroll
            for (int j=0;j<8;j++) acc[i][j] = make_float4(0.f,0.f,0.f,0.f);

        Pref1 pf[2];
        int it_row[2], it_k0l[2], it_i0[2], it_i1[2];
        #pragma unroll
        for (int it = 0; it < 2; it++){
            int g = tid + it*256;
            it_row[it] = g >> 2;
            it_k0l[it] = (g & 3) * 8;
            it_i0[it] = s_i0[it_row[it]];
            it_i1[it] = s_i1[it_row[it]];
        }

        #pragma unroll
        for (int it = 0; it < 2; it++)
            edge_ldg(it_i0[it], it_i1[it], it_k0l[it], pf[it]);
        #pragma unroll
        for (int it = 0; it < 2; it++){
            float v[8];
            edge_fin(pf[it], it_row[it], it_k0l[it], s_wt, s_tl, v);
            cvt_store(v, smem, (u32)(it_row[it]*80 + it_k0l[it]*2));
        }
        __syncthreads();

        #pragma unroll
        for (int s = 0; s < 4; s++){
            if (s + 1 < 4){
                #pragma unroll
                for (int it = 0; it < 2; it++)
                    edge_ldg(it_i0[it], it_i1[it], (s+1)*32 + it_k0l[it], pf[it]);
            }
            {
                u32 abuf = sb + (u32)((s & 1) * 20480) + a_rd;
                #pragma unroll
                for (int ka = 0; ka < 2; ka++){
                    u32 ah[2][4], al[2][4];
                    u32 ab = abuf + ka*32;
                    ldsm4(ah[0][0],ah[0][1],ah[0][2],ah[0][3], ab);
                    ldsm4(ah[1][0],ah[1][1],ah[1][2],ah[1][3], ab + 1280);
                    ldsm4(al[0][0],al[0][1],al[0][2],al[0][3], ab + 10240);
                    ldsm4(al[1][0],al[1][1],al[1][2],al[1][3], ab + 11520);
                    u32 bb0 = b_rd + (u32)((s*32 + ka*16) * 2);
                    #pragma unroll
                    for (int p = 0; p < 4; p++){
                        u32 h0,h1,h2,h3;
                        ldsm4(h0,h1,h2,h3, bb0 + p*4352);
                        #pragma unroll
                        for (int am = 0; am < 2; am++){
                            mma16816(acc[am][2*p],   ah[am], h0, h1);
                            mma16816(acc[am][2*p],   al[am], h0, h1);
                            mma16816(acc[am][2*p+1], ah[am], h2, h3);
                            mma16816(acc[am][2*p+1], al[am], h2, h3);
                        }
                    }
                }
            }
            if (s + 1 < 4){
                #pragma unroll
                for (int it = 0; it < 2; it++){
                    float v[8];
                    edge_fin(pf[it], it_row[it], (s+1)*32 + it_k0l[it], s_wt, s_tl, v);
                    cvt_store(v, smem, (u32)(((s+1)&1)*20480 + it_row[it]*80 + it_k0l[it]*2));
                }
            }
            __syncthreads();
        }

        // scatter: two 64-row phases staged in the A region.
        // Interior dst runs (unique global writer) use plain float4 stores into
        // the pre-zeroed agg; only runs touching a piece boundary with the same
        // dst on the other side need atomics. Bitwise identical results.
        float* s_red = (float*)smem;   // 64 x 132 floats
        #pragma unroll
        for (int phase = 0; phase < 2; phase++){
            if ((warp_m >> 1) == phase){
                #pragma unroll
                for (int am = 0; am < 2; am++)
                    #pragma unroll
                    for (int na = 0; na < 8; na++){
                        int ml = (warp_m & 1)*32 + am*16 + (lane >> 2);
                        int n0 = warp_n*64 + na*8 + (lane & 3)*2;
                        float b0 = s_bi[n0], b1 = s_bi[n0+1];
                        float4 c = acc[am][na];
                        s_red[ml*132 + n0]       = fmaxf(c.x + b0, 0.f);
                        s_red[ml*132 + n0 + 1]   = fmaxf(c.y + b1, 0.f);
                        s_red[(ml+8)*132 + n0]   = fmaxf(c.z + b0, 0.f);
                        s_red[(ml+8)*132 + n0+1] = fmaxf(c.w + b1, 0.f);
                    }
            }
            if (tid == 0) s_nh = 0;
            __syncthreads();
            if (tid < 64){
                int li = phase*64 + tid;
                int r = base + li;
                if (r < rows){
                    bool head = (tid == 0) || (s_i0[li] != s_i0[li-1]);
                    if (head){ int p = atomicAdd(&s_nh, 1); s_hd[p] = tid; }
                }
            }
            __syncthreads();
            int nh = s_nh;
            for (int item = tid; item < nh*32; item += 256){
                int h = s_hd[item >> 5];
                int strip = (item & 31) * 4;
                int d = s_i0[phase*64 + h];
                float a0=0.f, a1=0.f, a2=0.f, a3=0.f;
                int rr = h;
                while (rr < 64 && (base + phase*64 + rr) < rows && s_i0[phase*64 + rr] == d){
                    float* rp = &s_red[rr*132 + strip];
                    a0 += rp[0]; a1 += rp[1]; a2 += rp[2]; a3 += rp[3];
                    rr++;
                }
                int gstart = base + phase*64 + h;
                int gend   = base + phase*64 + rr;
                bool prev_same = (gstart > 0) && (g_sdst[gstart-1] == d);
                bool next_same = (rr == 64) && (gend < rows) && (g_sdst[gend] == d);
                if (!prev_same && !next_same){
                    *(float4*)&out[(size_t)d*HH + strip] = make_float4(a0,a1,a2,a3);
                } else {
                    atomicAdd(&out[(size_t)d*HH + strip + 0], a0);
                    atomicAdd(&out[(size_t)d*HH + strip + 1], a1);
                    atomicAdd(&out[(size_t)d*HH + strip + 2], a2);
                    atomicAdd(&out[(size_t)d*HH + strip + 3], a3);
                }
            }
            __syncthreads();
        }
    }
}

// ======================================================================
// FUSED Pd+Ps kernel (1 CTA/SM). Proven R10/R12/R13.
// ======================================================================
struct PO {
    static constexpr int B0 = 81920;
    static constexpr int B1 = 116736;
    static constexpr int BA = 151552;
    static constexpr int BC = BA + 512;
    static constexpr int BI = BC + 512;
    static constexpr int TOT = BI + 512;
};

__global__ __launch_bounds__(256, 1)
void gemm_pdps(const char* __restrict__ Bimg0, const char* __restrict__ Bimg1,
               const float* __restrict__ bias0,
               float* __restrict__ out0, float* __restrict__ out1, int rows)
{
    extern __shared__ __align__(16) char smem[];
    const u32 sb  = smem_u32(smem);
    const int tid = threadIdx.x;
    const int wid = tid >> 5;
    const int lane = tid & 31;

    float* s_ba = (float*)(smem + PO::BA);
    float* s_bc = (float*)(smem + PO::BC);
    float* s_bi = (float*)(smem + PO::BI);

    {
        const uint4* b0 = (const uint4*)Bimg0;
        const uint4* b1 = (const uint4*)Bimg1;
        for (int i = tid; i < 2048; i += 256){
            int row = i >> 4, cc = i & 15;
            *(uint4*)(smem + PO::B0 + row*272 + cc*16) = b0[i];
            *(uint4*)(smem + PO::B1 + row*272 + cc*16) = b1[i];
        }
    }
    if (tid < 128){
        s_ba[tid] = g_ba[tid];
        s_bc[tid] = g_bc[tid];
        s_bi[tid] = bias0[tid];
    }

    const int warp_m = wid & 3;
    const int warp_n = wid >> 2;
    const int qi = lane & 7, qd = lane >> 3;
    const u32 a_rd  = (u32)((warp_m*32 + (qd&1)*8 + qi)*80 + (qd>>1)*16);
    const u32 b_off = (u32)((warp_n*64 + (qd>>1)*8 + qi)*272 + (qd&1)*16);

    for (int base = blockIdx.x * 128; base < rows; base += gridDim.x * 128){
        __syncthreads();

        #pragma unroll
        for (int it = 0; it < 2; it++){
            int g = tid + it*256;
            int row = g >> 2;
            int k0l = (g & 3) * 8;
            int arow = min(base + row, rows - 1);
            #pragma unroll
            for (int s = 0; s < 4; s++){
                int kg = s*32 + k0l;
                float4 a0 = *(const float4*)&g_hn[(size_t)arow*HH + kg];
                float4 a1 = *(const float4*)&g_hn[(size_t)arow*HH + kg + 4];
                float v[8] = {a0.x,a0.y,a0.z,a0.w,a1.x,a1.y,a1.z,a1.w};
                #pragma unroll
                for (int kk = 0; kk < 8; kk++)
                    v[kk] = s_ba[kg+kk]*v[kk] + s_bc[kg+kk];
                cvt_store(v, smem, (u32)(s*20480 + row*80 + k0l*2));
            }
        }
        __syncthreads();

        #pragma unroll
        for (int pass = 0; pass < 2; pass++){
            const u32 b_rd = sb + (pass ? PO::B1 : PO::B0) + b_off;
            float4 acc[2][8];
            #pragma unroll
            for (int i=0;i<2;i++)
                #pragma unroll
                for (int j=0;j<8;j++) acc[i][j] = make_float4(0.f,0.f,0.f,0.f);

            #pragma unroll
            for (int s = 0; s < 4; s++){
                u32 abuf = sb + (u32)(s * 20480) + a_rd;
                #pragma unroll
                for (int ka = 0; ka < 2; ka++){
                    u32 ah[2][4], al[2][4];
                    u32 ab = abuf + ka*32;
                    ldsm4(ah[0][0],ah[0][1],ah[0][2],ah[0][3], ab);
                    ldsm4(ah[1][0],ah[1][1],ah[1][2],ah[1][3], ab + 1280);
                    ldsm4(al[0][0],al[0][1],al[0][2],al[0][3], ab + 10240);
                    ldsm4(al[1][0],al[1][1],al[1][2],al[1][3], ab + 11520);
                    u32 bb0 = b_rd + (u32)((s*32 + ka*16) * 2);
                    #pragma unroll
                    for (int p = 0; p < 4; p++){
                        u32 h0,h1,h2,h3;
                        ldsm4(h0,h1,h2,h3, bb0 + p*4352);
                        #pragma unroll
                        for (int am = 0; am < 2; am++){
                            mma16816(acc[am][2*p],   ah[am], h0, h1);
                            mma16816(acc[am][2*p],   al[am], h0, h1);
                            mma16816(acc[am][2*p+1], ah[am], h2, h3);
                            mma16816(acc[am][2*p+1], al[am], h2, h3);
                        }
                    }
                }
            }

            float* outp = pass ? out1 : out0;
            #pragma unroll
            for (int am = 0; am < 2; am++)
                #pragma unroll
                for (int na = 0; na < 8; na++){
                    int m0 = warp_m*32 + am*16 + (lane >> 2);
                    int n0 = warp_n*64 + na*8 + (lane & 3)*2;
                    float b0 = pass ? 0.f : s_bi[n0];
                    float b1 = pass ? 0.f : s_bi[n0+1];
                    float4 c = acc[am][na];
                    int r0 = base + m0;
                    if (r0 < rows){
                        *(float2*)&outp[(size_t)r0*HH + n0] = make_float2(c.x + b0, c.y + b1);
                        if (pass) *(float2*)&g_agg[(size_t)r0*HH + n0] = make_float2(0.f, 0.f);
                    }
                    if (r0 + 8 < rows){
                        *(float2*)&outp[(size_t)(r0+8)*HH + n0] = make_float2(c.z + b0, c.w + b1);
                        if (pass) *(float2*)&g_agg[(size_t)(r0+8)*HH + n0] = make_float2(0.f, 0.f);
                    }
                }
        }
    }
}

// ======================================================================
// Chunk-loop GEMM (u1 / u2), 2 CTAs/SM. Proven R10/R13. Optional fused fin.
// ======================================================================
#define MO_A_HI   0
#define MO_A_LO   10240
#define MO_B_HI   20480
#define MO_F0     71168
#define MO_F1     71680
#define MO_BA     72192
#define MO_BC     72704
#define MO_WV     73216
#define MO_SMEM   73728

template<int AMODE, bool ARELU>
__device__ __forceinline__ void a_frag8(const float* __restrict__ A, int arow,
    int kglob, float invd,
    const float* __restrict__ s_ba, const float* __restrict__ s_bc, float* v)
{
    if (AMODE == 0){
        float4 a0 = *(const float4*)&A[(size_t)arow*128 + kglob];
        float4 a1 = *(const float4*)&A[(size_t)arow*128 + kglob + 4];
        v[0]=a0.x; v[1]=a0.y; v[2]=a0.z; v[3]=a0.w;
        v[4]=a1.x; v[5]=a1.y; v[6]=a1.z; v[7]=a1.w;
    } else if (AMODE == 2){
        if (kglob < 128){
            float4 a0 = *(const float4*)&g_hn[(size_t)arow*HH + kglob];
            float4 a1 = *(const float4*)&g_hn[(size_t)arow*HH + kglob + 4];
            v[0]=a0.x; v[1]=a0.y; v[2]=a0.z; v[3]=a0.w;
            v[4]=a1.x; v[5]=a1.y; v[6]=a1.z; v[7]=a1.w;
            #pragma unroll
            for (int kk = 0; kk < 8; kk++)
                v[kk] = s_ba[kglob+kk]*v[kk] + s_bc[kglob+kk];
        } else {
            float4 a0 = *(const float4*)&g_agg[(size_t)arow*HH + (kglob-128)];
            float4 a1 = *(const float4*)&g_agg[(size_t)arow*HH + (kglob-128) + 4];
            v[0]=a0.x*invd; v[1]=a0.y*invd; v[2]=a0.z*invd; v[3]=a0.w*invd;
            v[4]=a1.x*invd; v[5]=a1.y*invd; v[6]=a1.z*invd; v[7]=a1.w*invd;
        }
    } else { // AMODE 3
        float4 a0 = *(const float4*)&A[(size_t)arow*128 + kglob];
        float4 a1 = *(const float4*)&A[(size_t)arow*128 + kglob + 4];
        v[0]=a0.x; v[1]=a0.y; v[2]=a0.z; v[3]=a0.w;
        v[4]=a1.x; v[5]=a1.y; v[6]=a1.z; v[7]=a1.w;
        #pragma unroll
        for (int kk = 0; kk < 8; kk++){
            v[kk] = s_ba[kglob+kk]*v[kk] + s_bc[kglob+kk];
            if (ARELU) v[kk] = fmaxf(v[kk], 0.f);
        }
    }
}

template<int AMODE, int EPI, bool ARELU, bool LASTFIN>
__global__ __launch_bounds__(256, 2)
void gemm_mma(const float* __restrict__ A, const char* __restrict__ Bimg,
              const float* __restrict__ bias, float* __restrict__ out,
              const float* __restrict__ wv, int rows, int K, int nchunks,
              const float* __restrict__ fg, const float* __restrict__ fb)
{
    extern __shared__ __align__(16) char smem[];
    const u32 sb  = smem_u32(smem);
    const int tid = threadIdx.x;
    const int wid = tid >> 5;
    const int lane = tid & 31;

    float*  s_f0 = (float*) (smem + MO_F0);
    float*  s_f1 = (float*) (smem + MO_F1);
    float*  s_ba = (float*) (smem + MO_BA);
    float*  s_bc = (float*) (smem + MO_BC);
    float*  s_wv = (float*) (smem + MO_WV);

    const int warp_m = wid & 3;
    const int warp_n = wid >> 2;
    const int qi = lane & 7, qd = lane >> 3;
    const u32 aab = sb + MO_A_HI + (u32)((warp_m*32 + (qd&1)*8 + qi)*80 + (qd>>1)*16);
    const u32 bab = sb + MO_B_HI + (u32)((warp_n*64 + (qd>>1)*8 + qi)*272 + (qd&1)*16);

    for (int base = blockIdx.x * 128; base < rows; base += gridDim.x * 128){
        __syncthreads();
        if (tid < 128){
            if (AMODE == 2){
                int rc = min(base + tid, rows - 1);
                s_f0[tid] = g_invdeg[rc];
                s_f1[tid] = g_var[rc];
            }
            s_ba[tid] = g_ba[tid];
            s_bc[tid] = g_bc[tid];
            if (EPI == EPI_RELU_STORE_V) s_wv[tid] = wv[tid];
        }
        __syncthreads();

        float4 acc[2][8];
        #pragma unroll
        for (int i=0;i<2;i++)
            #pragma unroll
            for (int j=0;j<8;j++) acc[i][j] = make_float4(0.f,0.f,0.f,0.f);

        for (int sc = 0; sc < nchunks; sc++){
            __syncthreads();
            const uint4* bsrc = (const uint4*)(Bimg + (size_t)sc * 65536);
            #pragma unroll 4
            for (int i = tid; i < 2048; i += 256){
                int row = i >> 4, c = i & 15;
                *(uint4*)(smem + MO_B_HI + row*272 + c*16) = bsrc[i];
            }
            const int nsub = min(4, (K - sc*128 + 31) >> 5);
            for (int sub = 0; sub < nsub; sub++){
                __syncthreads();
                #pragma unroll 1
                for (int g = tid; g < 512; g += 256){
                    int row = g >> 2;
                    int k0l = (g & 3) * 8;
                    int kglob = sc*128 + sub*32 + k0l;
                    int arow = min(base + row, rows - 1);
                    float v[8];
                    a_frag8<AMODE, ARELU>(A, arow, kglob,
                                          AMODE==2 ? s_f0[row] : 0.f,
                                          s_ba, s_bc, v);
                    u32 hw[4], lw[4];
                    split8(v, hw, lw);
                    u32 aoff = (u32)(row*80 + k0l*2);
                    *(uint4*)(smem + MO_A_HI + aoff) = make_uint4(hw[0],hw[1],hw[2],hw[3]);
                    *(uint4*)(smem + MO_A_LO + aoff) = make_uint4(lw[0],lw[1],lw[2],lw[3]);
                }
                __syncthreads();
                #pragma unroll
                for (int ka = 0; ka < 2; ka++){
                    u32 ah[2][4], al[2][4];
                    u32 ab = aab + ka*32;
                    ldsm4(ah[0][0],ah[0][1],ah[0][2],ah[0][3], ab);
                    ldsm4(ah[1][0],ah[1][1],ah[1][2],ah[1][3], ab + 1280);
                    ldsm4(al[0][0],al[0][1],al[0][2],al[0][3], ab + 10240);
                    ldsm4(al[1][0],al[1][1],al[1][2],al[1][3], ab + 11520);
                    u32 bb0 = bab + (u32)((sub*32 + ka*16) * 2);
                    #pragma unroll
                    for (int p = 0; p < 4; p++){
                        u32 h0,h1,h2,h3;
                        ldsm4(h0,h1,h2,h3, bb0 + p*4352);
                        #pragma unroll
                        for (int am = 0; am < 2; am++){
                            mma16816(acc[am][2*p],   ah[am], h0, h1);
                            mma16816(acc[am][2*p],   al[am], h0, h1);
                            mma16816(acc[am][2*p+1], ah[am], h2, h3);
                            mma16816(acc[am][2*p+1], al[am], h2, h3);
                        }
                    }
                }
            }
        }

        __syncthreads();
        float* s_red = (float*)smem;
        #pragma unroll
        for (int am = 0; am < 2; am++)
            #pragma unroll
            for (int na = 0; na < 8; na++){
                int m0 = warp_m*32 + am*16 + (lane >> 2);
                int n0 = warp_n*64 + na*8 + (lane & 3)*2;
                float4 c = acc[am][na];
                *(float2*)&s_red[m0*132 + n0]     = make_float2(c.x, c.y);
                *(float2*)&s_red[(m0+8)*132 + n0] = make_float2(c.z, c.w);
            }
        __syncthreads();

        const bool STATS = (EPI == EPI_RESID_STATS) || (EPI == EPI_STORE_STATS);
        for (int i = tid; i < 4096; i += 256){
            int row = i >> 5, c4 = (i & 31)*4;
            int r = base + row;
            if (r >= rows) continue;
            float4 v  = *(float4*)&s_red[row*132 + c4];
            float4 bb = *(const float4*)&bias[c4];
            v.x += bb.x; v.y += bb.y; v.z += bb.z; v.w += bb.w;
            if (EPI == EPI_RELU_STORE_V){
                float vr = s_f1[row];
                v.x += vr*s_wv[c4+0];
                v.y += vr*s_wv[c4+1];
                v.z += vr*s_wv[c4+2];
                v.w += vr*s_wv[c4+3];
            }
            if (EPI == EPI_RELU_STORE || EPI == EPI_RESID_STATS || EPI == EPI_RELU_STORE_V){
                v.x = fmaxf(v.x, 0.f); v.y = fmaxf(v.y, 0.f);
                v.z = fmaxf(v.z, 0.f); v.w = fmaxf(v.w, 0.f);
            }
            if (EPI == EPI_RESID_STATS){
                float4 nv = *(const float4*)&out[(size_t)r*HH + c4];
                v.x += s_ba[c4+0]*nv.x + s_bc[c4+0];
                v.y += s_ba[c4+1]*nv.y + s_bc[c4+1];
                v.z += s_ba[c4+2]*nv.z + s_bc[c4+2];
                v.w += s_ba[c4+3]*nv.w + s_bc[c4+3];
            }
            *(float4*)&out[(size_t)r*HH + c4] = v;
            if (STATS) *(float4*)&s_red[row*132 + c4] = v;
        }
        if (STATS){
            __syncthreads();
            int nval = min(128, rows - base);
            if (tid < 128){
                float s = 0.f, s2 = 0.f;
                for (int rr = 0; rr < nval; rr++){
                    float v = s_red[rr*132 + tid];
                    s += v; s2 += v*v;
                }
                atomicAdd(&g_sum[tid], s);
                atomicAdd(&g_sumsq[tid], s2);
            }
        }
    }

    if (LASTFIN){
        __threadfence();
        __shared__ int s_rank;
        if (tid == 0) s_rank = atomicAdd(&g_tick, 1);
        __syncthreads();
        if (s_rank == (int)gridDim.x - 1){
            bn_fin_dev(tid, fg, fb);
            __threadfence();
            if (tid == 0) g_tick = 0;
        }
    }
}

// ======================================================================
// Embedding GEMM, 2 CTAs/SM (R12 layout) + fused BN2 fin. Proven R13.
// ======================================================================
#define EO_A_HI   0
#define EO_A_LO   10240
#define EO_B_HI   36864
#define EO_BA     71680
#define EO_BC     72192
#define EO_SMEM   72704

__global__ __launch_bounds__(256, 2)
void gemm_emb(const float* __restrict__ A, const char* __restrict__ Bimg,
              const float* __restrict__ bias, float* __restrict__ out, int rows,
              const float* __restrict__ fg, const float* __restrict__ fb)
{
    extern __shared__ __align__(16) char smem[];
    const u32 sb  = smem_u32(smem);
    const int tid = threadIdx.x;
    const int wid = tid >> 5;
    const int lane = tid & 31;

    float*  s_ba = (float*) (smem + EO_BA);
    float*  s_bc = (float*) (smem + EO_BC);

    const int warp_m = wid & 3;
    const int warp_n = wid >> 2;
    const int qi = lane & 7, qd = lane >> 3;
    const u32 aab = sb + EO_A_HI + (u32)((warp_m*32 + (qd&1)*8 + qi)*80 + (qd>>1)*16);
    const u32 bab = sb + EO_B_HI + (u32)((warp_n*64 + (qd>>1)*8 + qi)*272 + (qd&1)*16);

    {
        const uint4* bsrc = (const uint4*)Bimg;
        for (int i = tid; i < 2048; i += 256){
            int row = i >> 4, c = i & 15;
            *(uint4*)(smem + EO_B_HI + row*272 + c*16) = bsrc[i];
        }
    }
    if (tid < 128){
        s_ba[tid] = g_ba[tid];
        s_bc[tid] = g_bc[tid];
    }

    for (int base = blockIdx.x * 128; base < rows; base += gridDim.x * 128){
        float4 acc[2][8];
        #pragma unroll
        for (int i=0;i<2;i++)
            #pragma unroll
            for (int j=0;j<8;j++) acc[i][j] = make_float4(0.f,0.f,0.f,0.f);

        for (int sub = 0; sub < 4; sub++){
            __syncthreads();
            #pragma unroll 1
            for (int g = tid; g < 512; g += 256){
                int row = g >> 2;
                int k0l = (g & 3) * 8;
                int kglob = sub*32 + k0l;
                int arow = min(base + row, rows - 1);
                float4 a0 = *(const float4*)&A[(size_t)arow*128 + kglob];
                float4 a1 = *(const float4*)&A[(size_t)arow*128 + kglob + 4];
                float v[8] = {a0.x,a0.y,a0.z,a0.w,a1.x,a1.y,a1.z,a1.w};
                #pragma unroll
                for (int kk = 0; kk < 8; kk++)
                    v[kk] = fmaxf(s_ba[kglob+kk]*v[kk] + s_bc[kglob+kk], 0.f);
                u32 hw[4], lw[4];
                split8(v, hw, lw);
                u32 aoff = (u32)(row*80 + k0l*2);
                *(uint4*)(smem + EO_A_HI + aoff) = make_uint4(hw[0],hw[1],hw[2],hw[3]);
                *(uint4*)(smem + EO_A_LO + aoff) = make_uint4(lw[0],lw[1],lw[2],lw[3]);
            }
            __syncthreads();
            #pragma unroll
            for (int ka = 0; ka < 2; ka++){
                u32 ah[2][4], al[2][4];
                u32 ab = aab + ka*32;
                ldsm4(ah[0][0],ah[0][1],ah[0][2],ah[0][3], ab);
                ldsm4(ah[1][0],ah[1][1],ah[1][2],ah[1][3], ab + 1280);
                ldsm4(al[0][0],al[0][1],al[0][2],al[0][3], ab + 10240);
                ldsm4(al[1][0],al[1][1],al[1][2],al[1][3], ab + 11520);
                u32 bb0 = bab + (u32)((sub*32 + ka*16) * 2);
                #pragma unroll
                for (int p = 0; p < 4; p++){
                    u32 h0,h1,h2,h3;
                    ldsm4(h0,h1,h2,h3, bb0 + p*4352);
                    #pragma unroll
                    for (int am = 0; am < 2; am++){
                        mma16816(acc[am][2*p],   ah[am], h0, h1);
                        mma16816(acc[am][2*p],   al[am], h0, h1);
                        mma16816(acc[am][2*p+1], ah[am], h2, h3);
                        mma16816(acc[am][2*p+1], al[am], h2, h3);
                    }
                }
            }
        }

        __syncthreads();
        float* s_red = (float*)smem;   // 64 x 132 floats = 33,792 B < EO_B_HI
        #pragma unroll
        for (int phase = 0; phase < 2; phase++){
            if ((warp_m >> 1) == phase){
                #pragma unroll
                for (int am = 0; am < 2; am++)
                    #pragma unroll
                    for (int na = 0; na < 8; na++){
                        int ml = (warp_m & 1)*32 + am*16 + (lane >> 2);
                        int m0 = phase*64 + ml;
                        int n0 = warp_n*64 + na*8 + (lane & 3)*2;
                        float4 c = acc[am][na];
                        float bx = bias[n0], by = bias[n0+1];
                        float v0 = c.x + bx, v1 = c.y + by;
                        float v2 = c.z + bx, v3 = c.w + by;
                        s_red[ml*132 + n0]       = v0;
                        s_red[ml*132 + n0+1]     = v1;
                        s_red[(ml+8)*132 + n0]   = v2;
                        s_red[(ml+8)*132 + n0+1] = v3;
                        int r0 = base + m0;
                        if (r0 < rows)     *(float2*)&out[(size_t)r0*HH + n0]     = make_float2(v0,v1);
                        if (r0 + 8 < rows) *(float2*)&out[(size_t)(r0+8)*HH + n0] = make_float2(v2,v3);
                    }
            }
            __syncthreads();
            int nval = min(64, rows - base - phase*64);
            if (tid < 128 && nval > 0){
                float s = 0.f, s2 = 0.f;
                for (int rr = 0; rr < nval; rr++){
                    float v = s_red[rr*132 + tid];
                    s += v; s2 += v*v;
                }
                atomicAdd(&g_sum[tid], s);
                atomicAdd(&g_sumsq[tid], s2);
            }
            __syncthreads();
        }
    }

    // fused BN2 fin
    __threadfence();
    __shared__ int s_rank;
    if (tid == 0) s_rank = atomicAdd(&g_tick, 1);
    __syncthreads();
    if (s_rank == (int)gridDim.x - 1){
        bn_fin_dev(tid, fg, fb);
        __threadfence();
        if (tid == 0) g_tick = 0;
    }
}

// ---------------- ONE-SHOT weight image prep (all 43 chunks) ----------------
__global__ void k_prepB_all(const float* __restrict__ embW2,
                            const float* __restrict__ m1W,
                            const float* __restrict__ m2W,
                            const float* __restrict__ u1W,
                            const float* __restrict__ u2W,
                            char* __restrict__ img){
    int idx = blockIdx.x*blockDim.x + threadIdx.x;
    if (idx >= NCHUNK_TOT * 16384) return;
    int c = idx >> 14;
    int rem = idx & 16383;
    int n = rem & 127;
    int kcol = rem >> 7;

    const float* W;
    if (c == 0){
        W = embW2;
    } else {
        int l = (c - 1) / 7;
        int r = (c - 1) % 7;
        if      (r == 0) W = m1W + (size_t)l*260*128;
        else if (r == 1) W = m1W + (size_t)l*260*128 + 128*128;
        else if (r == 2) W = m2W + (size_t)l*128*128;
        else if (r == 3) W = u1W + (size_t)l*257*128;
        else if (r == 4) W = u1W + (size_t)l*257*128 + 128*128;
        else if (r == 6) W = u2W + (size_t)l*128*128;
        else return;
    }
    float w = W[(size_t)kcol*128 + n];
    ((__half*)(img + (size_t)c*65536))[n*128 + kcol] = __float2half_rn(w);
}

// ---------------- small kernels ----------------
__global__ void k_pre(const float* __restrict__ pos){
    int n = blockIdx.x*blockDim.x + threadIdx.x;
    if (n < NN){ g_var[n] = pos[n*3+0]; g_cnt[n] = 0; }
}
__global__ void k_hist(const int* __restrict__ dst){
    int e = blockIdx.x*blockDim.x + threadIdx.x;
    if (e < NE) atomicAdd(&g_cnt[dst[e]], 1);
}
#define SBK 512
__global__ __launch_bounds__(SBK)
void k_scanA(){
    __shared__ int sd[SBK];
    int b = blockIdx.x, t = threadIdx.x;
    int i = b*SBK + t;
    int c = (i < NN) ? g_cnt[i] : 0;
    sd[t] = c; __syncthreads();
    for (int off = 1; off < SBK; off <<= 1){
        int add = (t >= off) ? sd[t-off] : 0;
        __syncthreads();
        sd[t] += add;
        __syncthreads();
    }
    if (i < NN) g_woff[i] = sd[t] - c;
    if (t == SBK-1) g_bsum[b] = sd[t];
}
__global__ void k_scanB(int nb){
    __shared__ int s[128];
    int t = threadIdx.x;
    s[t] = (t < nb) ? g_bsum[t] : 0;
    __syncthreads();
    if (t == 0){
        int run = 0;
        for (int i = 0; i < nb; i++){ int c = s[i]; s[i] = run; run += c; }
    }
    __syncthreads();
    if (t < nb) g_bsum[t] = s[t];
}
__global__ void k_scanC(){
    int i = blockIdx.x*blockDim.x + threadIdx.x;
    if (i < NN){
        g_woff[i] += g_bsum[i / SBK];
        g_invdeg[i] = 1.f / fmaxf((float)g_cnt[i], 1.f);
    }
}
__global__ void k_scatter(const float* __restrict__ u, const float* __restrict__ pos,
                          const int* __restrict__ src, const int* __restrict__ dst){
    int e = blockIdx.x*blockDim.x + threadIdx.x;
    if (e < NE){
        int s = src[e], d = dst[e];
        int p = atomicAdd(&g_woff[d], 1);
        g_sdst[p] = d;
        g_ssrc[p] = s;
        g_tl[p] = make_float4(u[d]-u[s],
                              pos[d*3+1]-pos[s*3+1],
                              pos[d*3+2]-pos[s*3+2],
                              pos[d*3+0]);
    }
}
__global__ void k_h0(const float* __restrict__ u, const float* __restrict__ pos,
                     const float* __restrict__ W1, const float* __restrict__ b1){
    int idx = blockIdx.x*blockDim.x + threadIdx.x;
    if (idx < NN*HH){
        int n = idx >> 7, j = idx & 127;
        g_hn[idx] = u[n]       * W1[j]
                  + pos[n*3+1] * W1[128+j]
                  + pos[n*3+2] * W1[256+j]
                  + pos[n*3+0] * W1[384+j]
                  + b1[j];
    }
}
// stats of raw h0 + fused BN1 fin (last block)
__global__ void k_bn_stats(const float* __restrict__ x,
                           const float* __restrict__ fg, const float* __restrict__ fb){
    int j = threadIdx.x;
    int r0 = blockIdx.x * 256;
    int rend = min(r0 + 256, NN);
    float s = 0.f, s2 = 0.f;
    for (int r = r0; r < rend; r++){
        float v = x[(size_t)r*HH + j];
        s += v; s2 += v*v;
    }
    atomicAdd(&g_sum[j], s);
    atomicAdd(&g_sumsq[j], s2);
    __threadfence();
    __shared__ int s_rank;
    if (j == 0) s_rank = atomicAdd(&g_tick, 1);
    __syncthreads();
    if (s_rank == (int)gridDim.x - 1){
        bn_fin_dev(j, fg, fb);
        __threadfence();
        if (j == 0) g_tick = 0;
    }
}

// ---------------- CNN head ----------------
__global__ __launch_bounds__(64)
void k_cnn(const float* __restrict__ c1W, const float* __restrict__ c1b,
           const float* __restrict__ c2W, const float* __restrict__ c2b,
           const float* __restrict__ c3W, const float* __restrict__ c3b,
           float* __restrict__ out){
    __shared__ float sx[64][129];
    __shared__ float w1[64], w2[384], w3[64], b1[4], b2[8], b3[1];
    int tid = threadIdx.x;
    int base = blockIdx.x * 64;

    w1[tid] = c1W[tid];
    w3[tid] = c3W[tid];
    for (int i = tid; i < 384; i += 64) w2[i] = c2W[i];
    if (tid < 4) b1[tid] = c1b[tid];
    if (tid < 8) b2[tid] = c2b[tid];
    if (tid == 0) b3[0] = c3b[0];

    float a0 = g_ba[tid],    c0 = g_bc[tid];
    float a1_ = g_ba[tid+64], c1_ = g_bc[tid+64];
    for (int r = 0; r < 64; r++){
        int row = base + r; int rr = row < NN ? row : NN-1;
        sx[r][tid]    = a0 * g_hn[(size_t)rr*HH + tid]      + c0;
        sx[r][tid+64] = a1_* g_hn[(size_t)rr*HH + tid + 64] + c1_;
    }
    __syncthreads();

    int node = base + tid;
    if (node >= NN) return;

    float o1[4][38];
    #pragma unroll
    for (int c = 0; c < 4; c++)
        for (int p = 0; p < 38; p++){
            float s = b1[c];
            #pragma unroll
            for (int k = 0; k < 16; k++) s += sx[tid][3*p+k] * w1[c*16+k];
            o1[c][p] = fmaxf(s, 0.f);
        }
    float o2[8][9];
    for (int o = 0; o < 8; o++)
        for (int q = 0; q < 9; q++){
            float s = b2[o];
            for (int c = 0; c < 4; c++)
                #pragma unroll
                for (int k = 0; k < 12; k++) s += o1[c][3*q+k] * w2[(o*4+c)*12+k];
            o2[o][q] = fmaxf(s, 0.f);
        }
    float s = b3[0];
    #pragma unroll
    for (int o = 0; o < 8; o++)
        #pragma unroll
        for (int k = 0; k < 8; k++) s += o2[o][k] * w3[o*8+k];

    out[node] = 0.001f * s;
}

// ---------------- launch ----------------
extern "C" void kernel_launch(void* const* d_in, const int* in_sizes, int n_in,
                              void* d_out, int out_size)
{
    const float* u      = (const float*)d_in[0];
    const float* pos    = (const float*)d_in[1];
    const int*   ei     = (const int*)  d_in[2];
    const int*   src    = ei;
    const int*   dst    = ei + NE;
    const float* emb_W1 = (const float*)d_in[3];
    const float* emb_b1 = (const float*)d_in[4];
    const float* emb_g1 = (const float*)d_in[5];
    const float* emb_be1= (const float*)d_in[6];
    const float* emb_W2 = (const float*)d_in[7];
    const float* emb_b2 = (const float*)d_in[8];
    const float* emb_g2 = (const float*)d_in[9];
    const float* emb_be2= (const float*)d_in[10];
    const float* m1W    = (const float*)d_in[11];
    const float* m1b    = (const float*)d_in[12];
    const float* m2W    = (const float*)d_in[13];
    const float* m2b    = (const float*)d_in[14];
    const float* u1W    = (const float*)d_in[15];
    const float* u1b    = (const float*)d_in[16];
    const float* u2W    = (const float*)d_in[17];
    const float* u2b    = (const float*)d_in[18];
    const float* bng    = (const float*)d_in[19];
    const float* bnb    = (const float*)d_in[20];
    const float* c1W    = (const float*)d_in[21];
    const float* c1b    = (const float*)d_in[22];
    const float* c2W    = (const float*)d_in[23];
    const float* c2b    = (const float*)d_in[24];
    const float* c3W    = (const float*)d_in[25];
    const float* c3b    = (const float*)d_in[26];
    float* out = (float*)d_out;

    float *p_hn, *p_up, *p_agg, *p_Pd, *p_Ps;
    char *p_img;
    cudaGetSymbolAddress((void**)&p_hn,   g_hn);
    cudaGetSymbolAddress((void**)&p_up,   g_up);
    cudaGetSymbolAddress((void**)&p_agg,  g_agg);
    cudaGetSymbolAddress((void**)&p_Pd,   g_Pd);
    cudaGetSymbolAddress((void**)&p_Ps,   g_Ps);
    cudaGetSymbolAddress((void**)&p_img,  g_Bimg);

    cudaFuncSetAttribute(gemm_edge, cudaFuncAttributeMaxDynamicSharedMemorySize, FO::TOT);
    cudaFuncSetAttribute(gemm_pdps, cudaFuncAttributeMaxDynamicSharedMemorySize, PO::TOT);
    cudaFuncSetAttribute(gemm_emb,  cudaFuncAttributeMaxDynamicSharedMemorySize, EO_SMEM);
    cudaFuncSetAttribute(gemm_mma<2,EPI_RELU_STORE_V,false,false>, cudaFuncAttributeMaxDynamicSharedMemorySize, MO_SMEM);
    cudaFuncSetAttribute(gemm_mma<0,EPI_RESID_STATS,false,true>,   cudaFuncAttributeMaxDynamicSharedMemorySize, MO_SMEM);

    const int NB  = (NN + SBK - 1) / SBK;
    const int GO  = 296;   // 2-CTA/SM grids
    const int GF  = 304;
    const int GP  = 152;   // pdps (1 CTA/SM)

    auto chunk = [&](int idx) -> char* { return p_img + (size_t)idx * 65536; };

    // ---- prep ALL weight images in one launch ----
    k_prepB_all<<<(NCHUNK_TOT*16384+255)/256,256>>>(emb_W2, m1W, m2W, u1W, u2W, p_img);

    // ---- preprocessing ----
    k_pre<<<(NN+255)/256,256>>>(pos);
    k_hist<<<(NE+255)/256,256>>>(dst);
    k_scanA<<<NB,SBK>>>();
    k_scanB<<<1,128>>>(NB);
    k_scanC<<<(NN+255)/256,256>>>();
    k_scatter<<<(NE+255)/256,256>>>(u, pos, src, dst);

    // ---- embedding (BN1 fin fused into stats; BN2 fin fused into emb GEMM) ----
    k_h0<<<(NN*HH+255)/256,256>>>(u, pos, emb_W1, emb_b1);
    k_bn_stats<<<(NN+255)/256,128>>>(p_hn, emb_g1, emb_be1);
    gemm_emb<<<GO,256,EO_SMEM>>>(p_hn, chunk(0), emb_b2, p_hn, NN, emb_g2, emb_be2);

    // ---- message-passing layers ----
    for (int i = 0; i < LL; i++){
        const float* Wt = m1W + (size_t)i*260*128 + 256*128;
        const float* wv = u1W + (size_t)i*257*128 + 256*128;   // rank-1 var row of u1_W
        gemm_pdps<<<GP,256,PO::TOT>>>(chunk(1+i*7+0), chunk(1+i*7+1),
                                      m1b + i*128, p_Pd, p_Ps, NN);
        gemm_edge<<<GF,256,FO::TOT>>>(chunk(1+i*7+2), m2b + i*128, p_agg, Wt, NE);
        gemm_mma<2,EPI_RELU_STORE_V,false,false><<<GO,256,MO_SMEM>>>(
            nullptr, chunk(1+i*7+3), u1b + i*128, p_up, wv, NN, 256, 2, nullptr, nullptr);
        gemm_mma<0,EPI_RESID_STATS,false,true><<<GO,256,MO_SMEM>>>(
            p_up, chunk(1+i*7+6), u2b + i*128, p_hn, nullptr, NN, 128, 1,
            bng + i*128, bnb + i*128);
    }

    // ---- CNN head ----
    k_cnn<<<(NN+63)/64,64>>>(c1W, c1b, c2W, c2b, c3W, c3b, out);
}

// round 16
// speedup vs baseline: 1.0167x; 1.0167x over previous
#include <cuda_runtime.h>
#include <cuda_fp16.h>
#include <cstdint>

#define NN 50000
#define NE 600000
#define HH 128
#define LL 6

typedef unsigned long long u64;
typedef unsigned int u32;

// ---------------- scratch (static device buffers; no allocation) ----------------
__device__ float g_hn [NN*HH];      // raw pre-BN node tensor "n"
__device__ float g_up [NN*HH];
__device__ float g_agg[NN*HH];
__device__ float g_Pd [NN*HH];
__device__ float g_Ps [NN*HH];
__device__ float4 g_tl[NE];
__device__ int   g_sdst[NE];
__device__ int   g_ssrc[NE];
__device__ int   g_cnt[NN];
__device__ int   g_woff[NN];
__device__ int   g_bsum[128];
__device__ float g_invdeg[NN];
__device__ float g_var[NN];
__device__ float g_sum[HH];         // zero-init; every fin re-zeros (invariant)
__device__ float g_sumsq[HH];
__device__ float g_ba[HH];
__device__ float g_bc[HH];
__device__ int   g_tick;            // last-CTA ticket; zero-init; every fin re-zeros
#define NCHUNK_TOT 43
__device__ char g_Bimg[(size_t)NCHUNK_TOT * 65536];   // fp16 hi-limb [n][k], 32KB used/chunk

// ---------------- PTX helpers ----------------
__device__ __forceinline__ u32 smem_u32(const void* p){
    u32 a; asm("{ .reg .u64 t; cvta.to.shared.u64 t, %1; cvt.u32.u64 %0, t; }" : "=r"(a) : "l"(p));
    return a;
}
__device__ __forceinline__ void ldsm4(u32 &r0, u32 &r1, u32 &r2, u32 &r3, u32 addr){
    asm volatile("ldmatrix.sync.aligned.m8n8.x4.shared.b16 {%0,%1,%2,%3}, [%4];"
        : "=r"(r0), "=r"(r1), "=r"(r2), "=r"(r3) : "r"(addr));
}
__device__ __forceinline__ void mma16816(float4 &d, const u32* a, u32 b0, u32 b1){
    asm volatile("mma.sync.aligned.m16n8k16.row.col.f32.f16.f16.f32 "
        "{%0,%1,%2,%3}, {%4,%5,%6,%7}, {%8,%9}, {%0,%1,%2,%3};"
        : "+f"(d.x), "+f"(d.y), "+f"(d.z), "+f"(d.w)
        : "r"(a[0]), "r"(a[1]), "r"(a[2]), "r"(a[3]), "r"(b0), "r"(b1));
}
__device__ __forceinline__ u32 pack_h2(float v0, float v1){
    u32 r; asm("cvt.rn.f16x2.f32 %0, %1, %2;" : "=r"(r) : "f"(v1), "f"(v0)); return r;
}
__device__ __forceinline__ float trunc_hi(float v){
    return __uint_as_float(__float_as_uint(v) & 0xFFFFE000u);
}
__device__ __forceinline__ void split8(const float* v, u32* hw, u32* lw){
    #pragma unroll
    for (int q = 0; q < 4; q++){
        float h0 = trunc_hi(v[2*q]);
        float h1 = trunc_hi(v[2*q+1]);
        hw[q] = pack_h2(h0, h1);
        lw[q] = pack_h2(v[2*q] - h0, v[2*q+1] - h1);
    }
}

// BN fin: compute affine from stats, re-zero stats. Call with tid<128 active.
__device__ __forceinline__ void bn_fin_dev(int tid, const float* __restrict__ g,
                                           const float* __restrict__ be){
    if (tid < 128){
        float mu  = g_sum[tid]   * (1.f/NN);
        float var = g_sumsq[tid] * (1.f/NN) - mu*mu;
        float a = g[tid] * rsqrtf(var + 1e-5f);
        g_ba[tid] = a;
        g_bc[tid] = be[tid] - a*mu;
        g_sum[tid] = 0.f;
        g_sumsq[tid] = 0.f;
    }
}

// ======================================================================
// EDGE kernel (scatter GEMM), 2 CTAs/SM. Proven R13 (pure atomics).
// ======================================================================
struct FO {
    static constexpr int B0 = 40960;
    static constexpr int WT = B0 + 34816;
    static constexpr int I0 = WT + 2048;
    static constexpr int I1 = I0 + 512;
    static constexpr int TL = I1 + 512;
    static constexpr int BI = TL + 2048;
    static constexpr int TOT = BI + 512;
};

struct Pref1 { float4 x0, x1, y0, y1; };

__device__ __forceinline__ void edge_ldg(int i0, int i1, int kglob, Pref1& p){
    p.x0 = *(const float4*)&g_Pd[(size_t)i0*HH + kglob];
    p.x1 = *(const float4*)&g_Pd[(size_t)i0*HH + kglob + 4];
    p.y0 = *(const float4*)&g_Ps[(size_t)i1*HH + kglob];
    p.y1 = *(const float4*)&g_Ps[(size_t)i1*HH + kglob + 4];
}
__device__ __forceinline__ void edge_fin(const Pref1& p, int row, int kglob,
    const float* __restrict__ s_wt, const float4* __restrict__ s_tl, float* v)
{
    v[0]=p.x0.x+p.y0.x; v[1]=p.x0.y+p.y0.y; v[2]=p.x0.z+p.y0.z; v[3]=p.x0.w+p.y0.w;
    v[4]=p.x1.x+p.y1.x; v[5]=p.x1.y+p.y1.y; v[6]=p.x1.z+p.y1.z; v[7]=p.x1.w+p.y1.w;
    float4 tl = s_tl[row];
    #pragma unroll
    for (int t = 0; t < 4; t++){
        float tv = (&tl.x)[t];
        const float* wr = &s_wt[t*HH + kglob];
        #pragma unroll
        for (int kk = 0; kk < 8; kk++) v[kk] += tv * wr[kk];
    }
    #pragma unroll
    for (int kk = 0; kk < 8; kk++) v[kk] = fmaxf(v[kk], 0.f);
}

__device__ __forceinline__ void cvt_store(const float* v, char* smem, u32 aoff){
    u32 hw[4], lw[4];
    split8(v, hw, lw);
    *(uint4*)(smem + aoff)         = make_uint4(hw[0],hw[1],hw[2],hw[3]);
    *(uint4*)(smem + 10240 + aoff) = make_uint4(lw[0],lw[1],lw[2],lw[3]);
}

__global__ __launch_bounds__(256, 2)
void gemm_edge(const char* __restrict__ Bimg, const float* __restrict__ bias,
               float* __restrict__ out, const float* __restrict__ Wt, int rows)
{
    extern __shared__ __align__(16) char smem[];
    const u32 sb  = smem_u32(smem);
    const int tid = threadIdx.x;
    const int wid = tid >> 5;
    const int lane = tid & 31;

    int*    s_i0 = (int*)   (smem + FO::I0);
    int*    s_i1 = (int*)   (smem + FO::I1);
    float4* s_tl = (float4*)(smem + FO::TL);
    float*  s_bi = (float*) (smem + FO::BI);
    float*  s_wt = (float*) (smem + FO::WT);
    __shared__ int s_nh;
    __shared__ int s_hd[64];

    {
        const uint4* bsrc = (const uint4*)Bimg;
        for (int i = tid; i < 2048; i += 256){
            int row = i >> 4, cc = i & 15;
            *(uint4*)(smem + FO::B0 + row*272 + cc*16) = bsrc[i];
        }
    }
    for (int i = tid; i < 4*HH; i += 256) s_wt[i] = Wt[i];
    if (tid < 128) s_bi[tid] = bias[tid];

    const int warp_m = wid & 3;
    const int warp_n = wid >> 2;
    const int qi = lane & 7, qd = lane >> 3;
    const u32 a_rd = (u32)((warp_m*32 + (qd&1)*8 + qi)*80 + (qd>>1)*16);
    const u32 b_rd = sb + FO::B0 + (u32)((warp_n*64 + (qd>>1)*8 + qi)*272 + (qd&1)*16);

    for (int base = blockIdx.x * 128; base < rows; base += gridDim.x * 128){
        __syncthreads();
        if (tid < 128){
            int r = base + tid;
            bool v = r < rows;
            s_i0[tid] = v ? g_sdst[r] : 0;
            s_i1[tid] = v ? g_ssrc[r] : 0;
            s_tl[tid] = v ? g_tl[r]   : make_float4(0.f,0.f,0.f,0.f);
        }
        __syncthreads();

        float4 acc[2][8];
        #pragma unroll
        for (int i=0;i<2;i++)
            #pragma unroll
            for (int j=0;j<8;j++) acc[i][j] = make_float4(0.f,0.f,0.f,0.f);

        Pref1 pf[2];
        int it_row[2], it_k0l[2], it_i0[2], it_i1[2];
        #pragma unroll
        for (int it = 0; it < 2; it++){
            int g = tid + it*256;
            it_row[it] = g >> 2;
            it_k0l[it] = (g & 3) * 8;
            it_i0[it] = s_i0[it_row[it]];
            it_i1[it] = s_i1[it_row[it]];
        }

        #pragma unroll
        for (int it = 0; it < 2; it++)
            edge_ldg(it_i0[it], it_i1[it], it_k0l[it], pf[it]);
        #pragma unroll
        for (int it = 0; it < 2; it++){
            float v[8];
            edge_fin(pf[it], it_row[it], it_k0l[it], s_wt, s_tl, v);
            cvt_store(v, smem, (u32)(it_row[it]*80 + it_k0l[it]*2));
        }
        __syncthreads();

        #pragma unroll
        for (int s = 0; s < 4; s++){
            if (s + 1 < 4){
                #pragma unroll
                for (int it = 0; it < 2; it++)
                    edge_ldg(it_i0[it], it_i1[it], (s+1)*32 + it_k0l[it], pf[it]);
            }
            {
                u32 abuf = sb + (u32)((s & 1) * 20480) + a_rd;
                #pragma unroll
                for (int ka = 0; ka < 2; ka++){
                    u32 ah[2][4], al[2][4];
                    u32 ab = abuf + ka*32;
                    ldsm4(ah[0][0],ah[0][1],ah[0][2],ah[0][3], ab);
                    ldsm4(ah[1][0],ah[1][1],ah[1][2],ah[1][3], ab + 1280);
                    ldsm4(al[0][0],al[0][1],al[0][2],al[0][3], ab + 10240);
                    ldsm4(al[1][0],al[1][1],al[1][2],al[1][3], ab + 11520);
                    u32 bb0 = b_rd + (u32)((s*32 + ka*16) * 2);
                    #pragma unroll
                    for (int p = 0; p < 4; p++){
                        u32 h0,h1,h2,h3;
                        ldsm4(h0,h1,h2,h3, bb0 + p*4352);
                        #pragma unroll
                        for (int am = 0; am < 2; am++){
                            mma16816(acc[am][2*p],   ah[am], h0, h1);
                            mma16816(acc[am][2*p],   al[am], h0, h1);
                            mma16816(acc[am][2*p+1], ah[am], h2, h3);
                            mma16816(acc[am][2*p+1], al[am], h2, h3);
                        }
                    }
                }
            }
            if (s + 1 < 4){
                #pragma unroll
                for (int it = 0; it < 2; it++){
                    float v[8];
                    edge_fin(pf[it], it_row[it], (s+1)*32 + it_k0l[it], s_wt, s_tl, v);
                    cvt_store(v, smem, (u32)(((s+1)&1)*20480 + it_row[it]*80 + it_k0l[it]*2));
                }
            }
            __syncthreads();
        }

        // scatter: two 64-row phases staged in the A region (R13 proven)
        float* s_red = (float*)smem;   // 64 x 132 floats
        #pragma unroll
        for (int phase = 0; phase < 2; phase++){
            if ((warp_m >> 1) == phase){
                #pragma unroll
                for (int am = 0; am < 2; am++)
                    #pragma unroll
                    for (int na = 0; na < 8; na++){
                        int ml = (warp_m & 1)*32 + am*16 + (lane >> 2);
                        int n0 = warp_n*64 + na*8 + (lane & 3)*2;
                        float b0 = s_bi[n0], b1 = s_bi[n0+1];
                        float4 c = acc[am][na];
                        s_red[ml*132 + n0]       = fmaxf(c.x + b0, 0.f);
                        s_red[ml*132 + n0 + 1]   = fmaxf(c.y + b1, 0.f);
                        s_red[(ml+8)*132 + n0]   = fmaxf(c.z + b0, 0.f);
                        s_red[(ml+8)*132 + n0+1] = fmaxf(c.w + b1, 0.f);
                    }
            }
            if (tid == 0) s_nh = 0;
            __syncthreads();
            if (tid < 64){
                int li = phase*64 + tid;
                int r = base + li;
                if (r < rows){
                    bool head = (tid == 0) || (s_i0[li] != s_i0[li-1]);
                    if (head){ int p = atomicAdd(&s_nh, 1); s_hd[p] = tid; }
                }
            }
            __syncthreads();
            int nh = s_nh;
            for (int item = tid; item < nh*32; item += 256){
                int h = s_hd[item >> 5];
                int strip = (item & 31) * 4;
                int d = s_i0[phase*64 + h];
                float a0=0.f, a1=0.f, a2=0.f, a3=0.f;
                int rr = h;
                while (rr < 64 && (base + phase*64 + rr) < rows && s_i0[phase*64 + rr] == d){
                    float* rp = &s_red[rr*132 + strip];
                    a0 += rp[0]; a1 += rp[1]; a2 += rp[2]; a3 += rp[3];
                    rr++;
                }
                atomicAdd(&out[(size_t)d*HH + strip + 0], a0);
                atomicAdd(&out[(size_t)d*HH + strip + 1], a1);
                atomicAdd(&out[(size_t)d*HH + strip + 2], a2);
                atomicAdd(&out[(size_t)d*HH + strip + 3], a3);
            }
            __syncthreads();
        }
    }
}

// ======================================================================
// FUSED Pd+Ps kernel (1 CTA/SM). Proven R10/R12/R13.
// ======================================================================
struct PO {
    static constexpr int B0 = 81920;
    static constexpr int B1 = 116736;
    static constexpr int BA = 151552;
    static constexpr int BC = BA + 512;
    static constexpr int BI = BC + 512;
    static constexpr int TOT = BI + 512;
};

__global__ __launch_bounds__(256, 1)
void gemm_pdps(const char* __restrict__ Bimg0, const char* __restrict__ Bimg1,
               const float* __restrict__ bias0,
               float* __restrict__ out0, float* __restrict__ out1, int rows)
{
    extern __shared__ __align__(16) char smem[];
    const u32 sb  = smem_u32(smem);
    const int tid = threadIdx.x;
    const int wid = tid >> 5;
    const int lane = tid & 31;

    float* s_ba = (float*)(smem + PO::BA);
    float* s_bc = (float*)(smem + PO::BC);
    float* s_bi = (float*)(smem + PO::BI);

    {
        const uint4* b0 = (const uint4*)Bimg0;
        const uint4* b1 = (const uint4*)Bimg1;
        for (int i = tid; i < 2048; i += 256){
            int row = i >> 4, cc = i & 15;
            *(uint4*)(smem + PO::B0 + row*272 + cc*16) = b0[i];
            *(uint4*)(smem + PO::B1 + row*272 + cc*16) = b1[i];
        }
    }
    if (tid < 128){
        s_ba[tid] = g_ba[tid];
        s_bc[tid] = g_bc[tid];
        s_bi[tid] = bias0[tid];
    }

    const int warp_m = wid & 3;
    const int warp_n = wid >> 2;
    const int qi = lane & 7, qd = lane >> 3;
    const u32 a_rd  = (u32)((warp_m*32 + (qd&1)*8 + qi)*80 + (qd>>1)*16);
    const u32 b_off = (u32)((warp_n*64 + (qd>>1)*8 + qi)*272 + (qd&1)*16);

    for (int base = blockIdx.x * 128; base < rows; base += gridDim.x * 128){
        __syncthreads();

        #pragma unroll
        for (int it = 0; it < 2; it++){
            int g = tid + it*256;
            int row = g >> 2;
            int k0l = (g & 3) * 8;
            int arow = min(base + row, rows - 1);
            #pragma unroll
            for (int s = 0; s < 4; s++){
                int kg = s*32 + k0l;
                float4 a0 = *(const float4*)&g_hn[(size_t)arow*HH + kg];
                float4 a1 = *(const float4*)&g_hn[(size_t)arow*HH + kg + 4];
                float v[8] = {a0.x,a0.y,a0.z,a0.w,a1.x,a1.y,a1.z,a1.w};
                #pragma unroll
                for (int kk = 0; kk < 8; kk++)
                    v[kk] = s_ba[kg+kk]*v[kk] + s_bc[kg+kk];
                cvt_store(v, smem, (u32)(s*20480 + row*80 + k0l*2));
            }
        }
        __syncthreads();

        #pragma unroll
        for (int pass = 0; pass < 2; pass++){
            const u32 b_rd = sb + (pass ? PO::B1 : PO::B0) + b_off;
            float4 acc[2][8];
            #pragma unroll
            for (int i=0;i<2;i++)
                #pragma unroll
                for (int j=0;j<8;j++) acc[i][j] = make_float4(0.f,0.f,0.f,0.f);

            #pragma unroll
            for (int s = 0; s < 4; s++){
                u32 abuf = sb + (u32)(s * 20480) + a_rd;
                #pragma unroll
                for (int ka = 0; ka < 2; ka++){
                    u32 ah[2][4], al[2][4];
                    u32 ab = abuf + ka*32;
                    ldsm4(ah[0][0],ah[0][1],ah[0][2],ah[0][3], ab);
                    ldsm4(ah[1][0],ah[1][1],ah[1][2],ah[1][3], ab + 1280);
                    ldsm4(al[0][0],al[0][1],al[0][2],al[0][3], ab + 10240);
                    ldsm4(al[1][0],al[1][1],al[1][2],al[1][3], ab + 11520);
                    u32 bb0 = b_rd + (u32)((s*32 + ka*16) * 2);
                    #pragma unroll
                    for (int p = 0; p < 4; p++){
                        u32 h0,h1,h2,h3;
                        ldsm4(h0,h1,h2,h3, bb0 + p*4352);
                        #pragma unroll
                        for (int am = 0; am < 2; am++){
                            mma16816(acc[am][2*p],   ah[am], h0, h1);
                            mma16816(acc[am][2*p],   al[am], h0, h1);
                            mma16816(acc[am][2*p+1], ah[am], h2, h3);
                            mma16816(acc[am][2*p+1], al[am], h2, h3);
                        }
                    }
                }
            }

            float* outp = pass ? out1 : out0;
            #pragma unroll
            for (int am = 0; am < 2; am++)
                #pragma unroll
                for (int na = 0; na < 8; na++){
                    int m0 = warp_m*32 + am*16 + (lane >> 2);
                    int n0 = warp_n*64 + na*8 + (lane & 3)*2;
                    float b0 = pass ? 0.f : s_bi[n0];
                    float b1 = pass ? 0.f : s_bi[n0+1];
                    float4 c = acc[am][na];
                    int r0 = base + m0;
                    if (r0 < rows){
                        *(float2*)&outp[(size_t)r0*HH + n0] = make_float2(c.x + b0, c.y + b1);
                        if (pass) *(float2*)&g_agg[(size_t)r0*HH + n0] = make_float2(0.f, 0.f);
                    }
                    if (r0 + 8 < rows){
                        *(float2*)&outp[(size_t)(r0+8)*HH + n0] = make_float2(c.z + b0, c.w + b1);
                        if (pass) *(float2*)&g_agg[(size_t)(r0+8)*HH + n0] = make_float2(0.f, 0.f);
                    }
                }
        }
    }
}

// ======================================================================
// u1 kernel: K=256, BOTH B chunks resident, direct-register epilogue.
// 2 CTAs/SM (93.2 KB smem).
// ======================================================================
struct U1O {
    static constexpr int B0  = 20480;              // chunk c at B0 + c*34816
    static constexpr int F0  = 90112;
    static constexpr int F1  = F0 + 512;
    static constexpr int BA  = F1 + 512;
    static constexpr int BC  = BA + 512;
    static constexpr int B1O = BC + 512;
    static constexpr int WV  = B1O + 512;
    static constexpr int TOT = WV + 512;
};

__global__ __launch_bounds__(256, 2)
void gemm_u1(const char* __restrict__ Bimg, const float* __restrict__ b1,
             const float* __restrict__ wv, float* __restrict__ out, int rows)
{
    extern __shared__ __align__(16) char smem[];
    const u32 sb  = smem_u32(smem);
    const int tid = threadIdx.x;
    const int wid = tid >> 5;
    const int lane = tid & 31;

    float* s_f0 = (float*)(smem + U1O::F0);
    float* s_f1 = (float*)(smem + U1O::F1);
    float* s_ba = (float*)(smem + U1O::BA);
    float* s_bc = (float*)(smem + U1O::BC);
    float* s_b1 = (float*)(smem + U1O::B1O);
    float* s_wv = (float*)(smem + U1O::WV);

    // one-time: both B chunks + constants
    #pragma unroll
    for (int c = 0; c < 2; c++){
        const uint4* bsrc = (const uint4*)(Bimg + (size_t)c * 65536);
        for (int i = tid; i < 2048; i += 256){
            int row = i >> 4, cc = i & 15;
            *(uint4*)(smem + U1O::B0 + c*34816 + row*272 + cc*16) = bsrc[i];
        }
    }
    if (tid < 128){
        s_ba[tid] = g_ba[tid]; s_bc[tid] = g_bc[tid];
        s_b1[tid] = b1[tid];   s_wv[tid] = wv[tid];
    }

    const int warp_m = wid & 3;
    const int warp_n = wid >> 2;
    const int qi = lane & 7, qd = lane >> 3;
    const u32 a_rd = (u32)((warp_m*32 + (qd&1)*8 + qi)*80 + (qd>>1)*16);
    const u32 b_rd = sb + U1O::B0 + (u32)((warp_n*64 + (qd>>1)*8 + qi)*272 + (qd&1)*16);

    for (int base = blockIdx.x * 128; base < rows; base += gridDim.x * 128){
        __syncthreads();   // prev tile mma done (A safe); covers one-time loads on iter 0
        if (tid < 128){
            int rc = min(base + tid, rows - 1);
            s_f0[tid] = g_invdeg[rc];
            s_f1[tid] = g_var[rc];
        }
        __syncthreads();

        float4 acc[2][8];
        #pragma unroll
        for (int i=0;i<2;i++)
            #pragma unroll
            for (int j=0;j<8;j++) acc[i][j] = make_float4(0.f,0.f,0.f,0.f);

        for (int sub = 0; sub < 8; sub++){
            // ---- assemble A 128x32 ----
            #pragma unroll
            for (int it = 0; it < 2; it++){
                int g = tid + it*256;
                int row = g >> 2;
                int k0l = (g & 3) * 8;
                int kglob = sub*32 + k0l;
                int arow = min(base + row, rows - 1);
                float v[8];
                if (kglob < 128){
                    float4 a0 = *(const float4*)&g_hn[(size_t)arow*HH + kglob];
                    float4 a1 = *(const float4*)&g_hn[(size_t)arow*HH + kglob + 4];
                    v[0]=a0.x; v[1]=a0.y; v[2]=a0.z; v[3]=a0.w;
                    v[4]=a1.x; v[5]=a1.y; v[6]=a1.z; v[7]=a1.w;
                    #pragma unroll
                    for (int kk = 0; kk < 8; kk++)
                        v[kk] = s_ba[kglob+kk]*v[kk] + s_bc[kglob+kk];
                } else {
                    float invd = s_f0[row];
                    float4 a0 = *(const float4*)&g_agg[(size_t)arow*HH + (kglob-128)];
                    float4 a1 = *(const float4*)&g_agg[(size_t)arow*HH + (kglob-128) + 4];
                    v[0]=a0.x*invd; v[1]=a0.y*invd; v[2]=a0.z*invd; v[3]=a0.w*invd;
                    v[4]=a1.x*invd; v[5]=a1.y*invd; v[6]=a1.z*invd; v[7]=a1.w*invd;
                }
                cvt_store(v, smem, (u32)(row*80 + k0l*2));
            }
            __syncthreads();
            // ---- mma (B from resident chunk sub>>2) ----
            {
                u32 bchunk = b_rd + (u32)((sub >> 2) * 34816);
                #pragma unroll
                for (int ka = 0; ka < 2; ka++){
                    u32 ah[2][4], al[2][4];
                    u32 ab = sb + a_rd + ka*32;
                    ldsm4(ah[0][0],ah[0][1],ah[0][2],ah[0][3], ab);
                    ldsm4(ah[1][0],ah[1][1],ah[1][2],ah[1][3], ab + 1280);
                    ldsm4(al[0][0],al[0][1],al[0][2],al[0][3], ab + 10240);
                    ldsm4(al[1][0],al[1][1],al[1][2],al[1][3], ab + 11520);
                    u32 bb0 = bchunk + (u32)(((sub & 3)*32 + ka*16) * 2);
                    #pragma unroll
                    for (int p = 0; p < 4; p++){
                        u32 h0,h1,h2,h3;
                        ldsm4(h0,h1,h2,h3, bb0 + p*4352);
                        #pragma unroll
                        for (int am = 0; am < 2; am++){
                            mma16816(acc[am][2*p],   ah[am], h0, h1);
                            mma16816(acc[am][2*p],   al[am], h0, h1);
                            mma16816(acc[am][2*p+1], ah[am], h2, h3);
                            mma16816(acc[am][2*p+1], al[am], h2, h3);
                        }
                    }
                }
            }
            __syncthreads();   // mma reads done before next assemble overwrites A
        }

        // ---- direct-register epilogue: relu(acc + b1 + var*wv) -> out ----
        #pragma unroll
        for (int am = 0; am < 2; am++)
            #pragma unroll
            for (int na = 0; na < 8; na++){
                int m0 = warp_m*32 + am*16 + (lane >> 2);
                int n0 = warp_n*64 + na*8 + (lane & 3)*2;
                float4 c = acc[am][na];
                float bb0 = s_b1[n0], bb1 = s_b1[n0+1];
                float w0 = s_wv[n0],  w1 = s_wv[n0+1];
                float f1a = s_f1[m0], f1b = s_f1[m0+8];
                float v0 = fmaxf(c.x + bb0 + f1a*w0, 0.f);
                float v1 = fmaxf(c.y + bb1 + f1a*w1, 0.f);
                float v2 = fmaxf(c.z + bb0 + f1b*w0, 0.f);
                float v3 = fmaxf(c.w + bb1 + f1b*w1, 0.f);
                int r0 = base + m0;
                if (r0 < rows)     *(float2*)&out[(size_t)r0*HH + n0]     = make_float2(v0,v1);
                if (r0 + 8 < rows) *(float2*)&out[(size_t)(r0+8)*HH + n0] = make_float2(v2,v3);
            }
    }
}

// ======================================================================
// u2 kernel: K=128, B resident ABOVE the staging region; resid + stats +
// fused BN fin. 2 CTAs/SM (103.4 KB smem).
// ======================================================================
struct U2O {
    static constexpr int B  = 67584;               // above s_red (128x132 floats)
    static constexpr int BA = 102400;
    static constexpr int BC = BA + 512;
    static constexpr int TOT = BC + 512;
};

__global__ __launch_bounds__(256, 2)
void gemm_u2(const float* __restrict__ A, const char* __restrict__ Bimg,
             const float* __restrict__ bias, float* __restrict__ out, int rows,
             const float* __restrict__ fg, const float* __restrict__ fb)
{
    extern __shared__ __align__(16) char smem[];
    const u32 sb  = smem_u32(smem);
    const int tid = threadIdx.x;
    const int wid = tid >> 5;
    const int lane = tid & 31;

    float* s_ba = (float*)(smem + U2O::BA);
    float* s_bc = (float*)(smem + U2O::BC);

    {
        const uint4* bsrc = (const uint4*)Bimg;
        for (int i = tid; i < 2048; i += 256){
            int row = i >> 4, cc = i & 15;
            *(uint4*)(smem + U2O::B + row*272 + cc*16) = bsrc[i];
        }
    }
    if (tid < 128){
        s_ba[tid] = g_ba[tid];
        s_bc[tid] = g_bc[tid];
    }

    const int warp_m = wid & 3;
    const int warp_n = wid >> 2;
    const int qi = lane & 7, qd = lane >> 3;
    const u32 a_rd = (u32)((warp_m*32 + (qd&1)*8 + qi)*80 + (qd>>1)*16);
    const u32 b_rd = sb + U2O::B + (u32)((warp_n*64 + (qd>>1)*8 + qi)*272 + (qd&1)*16);

    for (int base = blockIdx.x * 128; base < rows; base += gridDim.x * 128){
        __syncthreads();   // prev epilogue done (s_red/A safe); covers one-time loads

        float4 acc[2][8];
        #pragma unroll
        for (int i=0;i<2;i++)
            #pragma unroll
            for (int j=0;j<8;j++) acc[i][j] = make_float4(0.f,0.f,0.f,0.f);

        for (int sub = 0; sub < 4; sub++){
            #pragma unroll
            for (int it = 0; it < 2; it++){
                int g = tid + it*256;
                int row = g >> 2;
                int k0l = (g & 3) * 8;
                int kglob = sub*32 + k0l;
                int arow = min(base + row, rows - 1);
                float4 a0 = *(const float4*)&A[(size_t)arow*128 + kglob];
                float4 a1 = *(const float4*)&A[(size_t)arow*128 + kglob + 4];
                float v[8] = {a0.x,a0.y,a0.z,a0.w,a1.x,a1.y,a1.z,a1.w};
                cvt_store(v, smem, (u32)(row*80 + k0l*2));
            }
            __syncthreads();
            #pragma unroll
            for (int ka = 0; ka < 2; ka++){
                u32 ah[2][4], al[2][4];
                u32 ab = sb + a_rd + ka*32;
                ldsm4(ah[0][0],ah[0][1],ah[0][2],ah[0][3], ab);
                ldsm4(ah[1][0],ah[1][1],ah[1][2],ah[1][3], ab + 1280);
                ldsm4(al[0][0],al[0][1],al[0][2],al[0][3], ab + 10240);
                ldsm4(al[1][0],al[1][1],al[1][2],al[1][3], ab + 11520);
                u32 bb0 = b_rd + (u32)((sub*32 + ka*16) * 2);
                #pragma unroll
                for (int p = 0; p < 4; p++){
                    u32 h0,h1,h2,h3;
                    ldsm4(h0,h1,h2,h3, bb0 + p*4352);
                    #pragma unroll
                    for (int am = 0; am < 2; am++){
                        mma16816(acc[am][2*p],   ah[am], h0, h1);
                        mma16816(acc[am][2*p],   al[am], h0, h1);
                        mma16816(acc[am][2*p+1], ah[am], h2, h3);
                        mma16816(acc[am][2*p+1], al[am], h2, h3);
                    }
                }
            }
            __syncthreads();
        }

        // staging epilogue (s_red at [0, 67584) — below resident B)
        float* s_red = (float*)smem;
        #pragma unroll
        for (int am = 0; am < 2; am++)
            #pragma unroll
            for (int na = 0; na < 8; na++){
                int m0 = warp_m*32 + am*16 + (lane >> 2);
                int n0 = warp_n*64 + na*8 + (lane & 3)*2;
                float4 c = acc[am][na];
                *(float2*)&s_red[m0*132 + n0]     = make_float2(c.x, c.y);
                *(float2*)&s_red[(m0+8)*132 + n0] = make_float2(c.z, c.w);
            }
        __syncthreads();

        for (int i = tid; i < 4096; i += 256){
            int row = i >> 5, c4 = (i & 31)*4;
            int r = base + row;
            if (r >= rows) continue;
            float4 v  = *(float4*)&s_red[row*132 + c4];
            float4 bb = *(const float4*)&bias[c4];
            v.x = fmaxf(v.x + bb.x, 0.f); v.y = fmaxf(v.y + bb.y, 0.f);
            v.z = fmaxf(v.z + bb.z, 0.f); v.w = fmaxf(v.w + bb.w, 0.f);
            float4 nv = *(const float4*)&out[(size_t)r*HH + c4];
            v.x += s_ba[c4+0]*nv.x + s_bc[c4+0];
            v.y += s_ba[c4+1]*nv.y + s_bc[c4+1];
            v.z += s_ba[c4+2]*nv.z + s_bc[c4+2];
            v.w += s_ba[c4+3]*nv.w + s_bc[c4+3];
            *(float4*)&out[(size_t)r*HH + c4] = v;
            *(float4*)&s_red[row*132 + c4] = v;
        }
        __syncthreads();
        {
            int nval = min(128, rows - base);
            if (tid < 128){
                float s = 0.f, s2 = 0.f;
                for (int rr = 0; rr < nval; rr++){
                    float v = s_red[rr*132 + tid];
                    s += v; s2 += v*v;
                }
                atomicAdd(&g_sum[tid], s);
                atomicAdd(&g_sumsq[tid], s2);
            }
        }
    }

    // fused BN fin for next layer
    __threadfence();
    __shared__ int s_rank;
    if (tid == 0) s_rank = atomicAdd(&g_tick, 1);
    __syncthreads();
    if (s_rank == (int)gridDim.x - 1){
        bn_fin_dev(tid, fg, fb);
        __threadfence();
        if (tid == 0) g_tick = 0;
    }
}

// ======================================================================
// Embedding GEMM, 2 CTAs/SM (R12 layout) + fused BN2 fin. Proven R13.
// ======================================================================
#define EO_A_HI   0
#define EO_A_LO   10240
#define EO_B_HI   36864
#define EO_BA     71680
#define EO_BC     72192
#define EO_SMEM   72704

__global__ __launch_bounds__(256, 2)
void gemm_emb(const float* __restrict__ A, const char* __restrict__ Bimg,
              const float* __restrict__ bias, float* __restrict__ out, int rows,
              const float* __restrict__ fg, const float* __restrict__ fb)
{
    extern __shared__ __align__(16) char smem[];
    const u32 sb  = smem_u32(smem);
    const int tid = threadIdx.x;
    const int wid = tid >> 5;
    const int lane = tid & 31;

    float*  s_ba = (float*) (smem + EO_BA);
    float*  s_bc = (float*) (smem + EO_BC);

    const int warp_m = wid & 3;
    const int warp_n = wid >> 2;
    const int qi = lane & 7, qd = lane >> 3;
    const u32 aab = sb + EO_A_HI + (u32)((warp_m*32 + (qd&1)*8 + qi)*80 + (qd>>1)*16);
    const u32 bab = sb + EO_B_HI + (u32)((warp_n*64 + (qd>>1)*8 + qi)*272 + (qd&1)*16);

    {
        const uint4* bsrc = (const uint4*)Bimg;
        for (int i = tid; i < 2048; i += 256){
            int row = i >> 4, c = i & 15;
            *(uint4*)(smem + EO_B_HI + row*272 + c*16) = bsrc[i];
        }
    }
    if (tid < 128){
        s_ba[tid] = g_ba[tid];
        s_bc[tid] = g_bc[tid];
    }

    for (int base = blockIdx.x * 128; base < rows; base += gridDim.x * 128){
        float4 acc[2][8];
        #pragma unroll
        for (int i=0;i<2;i++)
            #pragma unroll
            for (int j=0;j<8;j++) acc[i][j] = make_float4(0.f,0.f,0.f,0.f);

        for (int sub = 0; sub < 4; sub++){
            __syncthreads();
            #pragma unroll 1
            for (int g = tid; g < 512; g += 256){
                int row = g >> 2;
                int k0l = (g & 3) * 8;
                int kglob = sub*32 + k0l;
                int arow = min(base + row, rows - 1);
                float4 a0 = *(const float4*)&A[(size_t)arow*128 + kglob];
                float4 a1 = *(const float4*)&A[(size_t)arow*128 + kglob + 4];
                float v[8] = {a0.x,a0.y,a0.z,a0.w,a1.x,a1.y,a1.z,a1.w};
                #pragma unroll
                for (int kk = 0; kk < 8; kk++)
                    v[kk] = fmaxf(s_ba[kglob+kk]*v[kk] + s_bc[kglob+kk], 0.f);
                u32 hw[4], lw[4];
                split8(v, hw, lw);
                u32 aoff = (u32)(row*80 + k0l*2);
                *(uint4*)(smem + EO_A_HI + aoff) = make_uint4(hw[0],hw[1],hw[2],hw[3]);
                *(uint4*)(smem + EO_A_LO + aoff) = make_uint4(lw[0],lw[1],lw[2],lw[3]);
            }
            __syncthreads();
            #pragma unroll
            for (int ka = 0; ka < 2; ka++){
                u32 ah[2][4], al[2][4];
                u32 ab = aab + ka*32;
                ldsm4(ah[0][0],ah[0][1],ah[0][2],ah[0][3], ab);
                ldsm4(ah[1][0],ah[1][1],ah[1][2],ah[1][3], ab + 1280);
                ldsm4(al[0][0],al[0][1],al[0][2],al[0][3], ab + 10240);
                ldsm4(al[1][0],al[1][1],al[1][2],al[1][3], ab + 11520);
                u32 bb0 = bab + (u32)((sub*32 + ka*16) * 2);
                #pragma unroll
                for (int p = 0; p < 4; p++){
                    u32 h0,h1,h2,h3;
                    ldsm4(h0,h1,h2,h3, bb0 + p*4352);
                    #pragma unroll
                    for (int am = 0; am < 2; am++){
                        mma16816(acc[am][2*p],   ah[am], h0, h1);
                        mma16816(acc[am][2*p],   al[am], h0, h1);
                        mma16816(acc[am][2*p+1], ah[am], h2, h3);
                        mma16816(acc[am][2*p+1], al[am], h2, h3);
                    }
                }
            }
        }

        __syncthreads();
        float* s_red = (float*)smem;   // 64 x 132 floats = 33,792 B < EO_B_HI
        #pragma unroll
        for (int phase = 0; phase < 2; phase++){
            if ((warp_m >> 1) == phase){
                #pragma unroll
                for (int am = 0; am < 2; am++)
                    #pragma unroll
                    for (int na = 0; na < 8; na++){
                        int ml = (warp_m & 1)*32 + am*16 + (lane >> 2);
                        int m0 = phase*64 + ml;
                        int n0 = warp_n*64 + na*8 + (lane & 3)*2;
                        float4 c = acc[am][na];
                        float bx = bias[n0], by = bias[n0+1];
                        float v0 = c.x + bx, v1 = c.y + by;
                        float v2 = c.z + bx, v3 = c.w + by;
                        s_red[ml*132 + n0]       = v0;
                        s_red[ml*132 + n0+1]     = v1;
                        s_red[(ml+8)*132 + n0]   = v2;
                        s_red[(ml+8)*132 + n0+1] = v3;
                        int r0 = base + m0;
                        if (r0 < rows)     *(float2*)&out[(size_t)r0*HH + n0]     = make_float2(v0,v1);
                        if (r0 + 8 < rows) *(float2*)&out[(size_t)(r0+8)*HH + n0] = make_float2(v2,v3);
                    }
            }
            __syncthreads();
            int nval = min(64, rows - base - phase*64);
            if (tid < 128 && nval > 0){
                float s = 0.f, s2 = 0.f;
                for (int rr = 0; rr < nval; rr++){
                    float v = s_red[rr*132 + tid];
                    s += v; s2 += v*v;
                }
                atomicAdd(&g_sum[tid], s);
                atomicAdd(&g_sumsq[tid], s2);
            }
            __syncthreads();
        }
    }

    // fused BN2 fin
    __threadfence();
    __shared__ int s_rank;
    if (tid == 0) s_rank = atomicAdd(&g_tick, 1);
    __syncthreads();
    if (s_rank == (int)gridDim.x - 1){
        bn_fin_dev(tid, fg, fb);
        __threadfence();
        if (tid == 0) g_tick = 0;
    }
}

// ---------------- ONE-SHOT weight image prep (all 43 chunks) ----------------
__global__ void k_prepB_all(const float* __restrict__ embW2,
                            const float* __restrict__ m1W,
                            const float* __restrict__ m2W,
                            const float* __restrict__ u1W,
                            const float* __restrict__ u2W,
                            char* __restrict__ img){
    int idx = blockIdx.x*blockDim.x + threadIdx.x;
    if (idx >= NCHUNK_TOT * 16384) return;
    int c = idx >> 14;
    int rem = idx & 16383;
    int n = rem & 127;
    int kcol = rem >> 7;

    const float* W;
    if (c == 0){
        W = embW2;
    } else {
        int l = (c - 1) / 7;
        int r = (c - 1) % 7;
        if      (r == 0) W = m1W + (size_t)l*260*128;
        else if (r == 1) W = m1W + (size_t)l*260*128 + 128*128;
        else if (r == 2) W = m2W + (size_t)l*128*128;
        else if (r == 3) W = u1W + (size_t)l*257*128;
        else if (r == 4) W = u1W + (size_t)l*257*128 + 128*128;
        else if (r == 6) W = u2W + (size_t)l*128*128;
        else return;
    }
    float w = W[(size_t)kcol*128 + n];
    ((__half*)(img + (size_t)c*65536))[n*128 + kcol] = __float2half_rn(w);
}

// ---------------- small kernels ----------------
__global__ void k_pre(const float* __restrict__ pos){
    int n = blockIdx.x*blockDim.x + threadIdx.x;
    if (n < NN){ g_var[n] = pos[n*3+0]; g_cnt[n] = 0; }
}
__global__ void k_hist(const int* __restrict__ dst){
    int e = blockIdx.x*blockDim.x + threadIdx.x;
    if (e < NE) atomicAdd(&g_cnt[dst[e]], 1);
}
#define SBK 512
__global__ __launch_bounds__(SBK)
void k_scanA(){
    __shared__ int sd[SBK];
    int b = blockIdx.x, t = threadIdx.x;
    int i = b*SBK + t;
    int c = (i < NN) ? g_cnt[i] : 0;
    sd[t] = c; __syncthreads();
    for (int off = 1; off < SBK; off <<= 1){
        int add = (t >= off) ? sd[t-off] : 0;
        __syncthreads();
        sd[t] += add;
        __syncthreads();
    }
    if (i < NN) g_woff[i] = sd[t] - c;
    if (t == SBK-1) g_bsum[b] = sd[t];
}
__global__ void k_scanB(int nb){
    __shared__ int s[128];
    int t = threadIdx.x;
    s[t] = (t < nb) ? g_bsum[t] : 0;
    __syncthreads();
    if (t == 0){
        int run = 0;
        for (int i = 0; i < nb; i++){ int c = s[i]; s[i] = run; run += c; }
    }
    __syncthreads();
    if (t < nb) g_bsum[t] = s[t];
}
__global__ void k_scanC(){
    int i = blockIdx.x*blockDim.x + threadIdx.x;
    if (i < NN){
        g_woff[i] += g_bsum[i / SBK];
        g_invdeg[i] = 1.f / fmaxf((float)g_cnt[i], 1.f);
    }
}
__global__ void k_scatter(const float* __restrict__ u, const float* __restrict__ pos,
                          const int* __restrict__ src, const int* __restrict__ dst){
    int e = blockIdx.x*blockDim.x + threadIdx.x;
    if (e < NE){
        int s = src[e], d = dst[e];
        int p = atomicAdd(&g_woff[d], 1);
        g_sdst[p] = d;
        g_ssrc[p] = s;
        g_tl[p] = make_float4(u[d]-u[s],
                              pos[d*3+1]-pos[s*3+1],
                              pos[d*3+2]-pos[s*3+2],
                              pos[d*3+0]);
    }
}
__global__ void k_h0(const float* __restrict__ u, const float* __restrict__ pos,
                     const float* __restrict__ W1, const float* __restrict__ b1){
    int idx = blockIdx.x*blockDim.x + threadIdx.x;
    if (idx < NN*HH){
        int n = idx >> 7, j = idx & 127;
        g_hn[idx] = u[n]       * W1[j]
                  + pos[n*3+1] * W1[128+j]
                  + pos[n*3+2] * W1[256+j]
                  + pos[n*3+0] * W1[384+j]
                  + b1[j];
    }
}
// stats of raw h0 + fused BN1 fin (last block)
__global__ void k_bn_stats(const float* __restrict__ x,
                           const float* __restrict__ fg, const float* __restrict__ fb){
    int j = threadIdx.x;
    int r0 = blockIdx.x * 256;
    int rend = min(r0 + 256, NN);
    float s = 0.f, s2 = 0.f;
    for (int r = r0; r < rend; r++){
        float v = x[(size_t)r*HH + j];
        s += v; s2 += v*v;
    }
    atomicAdd(&g_sum[j], s);
    atomicAdd(&g_sumsq[j], s2);
    __threadfence();
    __shared__ int s_rank;
    if (j == 0) s_rank = atomicAdd(&g_tick, 1);
    __syncthreads();
    if (s_rank == (int)gridDim.x - 1){
        bn_fin_dev(j, fg, fb);
        __threadfence();
        if (j == 0) g_tick = 0;
    }
}

// ---------------- CNN head ----------------
__global__ __launch_bounds__(64)
void k_cnn(const float* __restrict__ c1W, const float* __restrict__ c1b,
           const float* __restrict__ c2W, const float* __restrict__ c2b,
           const float* __restrict__ c3W, const float* __restrict__ c3b,
           float* __restrict__ out){
    __shared__ float sx[64][129];
    __shared__ float w1[64], w2[384], w3[64], b1[4], b2[8], b3[1];
    int tid = threadIdx.x;
    int base = blockIdx.x * 64;

    w1[tid] = c1W[tid];
    w3[tid] = c3W[tid];
    for (int i = tid; i < 384; i += 64) w2[i] = c2W[i];
    if (tid < 4) b1[tid] = c1b[tid];
    if (tid < 8) b2[tid] = c2b[tid];
    if (tid == 0) b3[0] = c3b[0];

    float a0 = g_ba[tid],    c0 = g_bc[tid];
    float a1_ = g_ba[tid+64], c1_ = g_bc[tid+64];
    for (int r = 0; r < 64; r++){
        int row = base + r; int rr = row < NN ? row : NN-1;
        sx[r][tid]    = a0 * g_hn[(size_t)rr*HH + tid]      + c0;
        sx[r][tid+64] = a1_* g_hn[(size_t)rr*HH + tid + 64] + c1_;
    }
    __syncthreads();

    int node = base + tid;
    if (node >= NN) return;

    float o1[4][38];
    #pragma unroll
    for (int c = 0; c < 4; c++)
        for (int p = 0; p < 38; p++){
            float s = b1[c];
            #pragma unroll
            for (int k = 0; k < 16; k++) s += sx[tid][3*p+k] * w1[c*16+k];
            o1[c][p] = fmaxf(s, 0.f);
        }
    float o2[8][9];
    for (int o = 0; o < 8; o++)
        for (int q = 0; q < 9; q++){
            float s = b2[o];
            for (int c = 0; c < 4; c++)
                #pragma unroll
                for (int k = 0; k < 12; k++) s += o1[c][3*q+k] * w2[(o*4+c)*12+k];
            o2[o][q] = fmaxf(s, 0.f);
        }
    float s = b3[0];
    #pragma unroll
    for (int o = 0; o < 8; o++)
        #pragma unroll
        for (int k = 0; k < 8; k++) s += o2[o][k] * w3[o*8+k];

    out[node] = 0.001f * s;
}

// ---------------- launch ----------------
extern "C" void kernel_launch(void* const* d_in, const int* in_sizes, int n_in,
                              void* d_out, int out_size)
{
    const float* u      = (const float*)d_in[0];
    const float* pos    = (const float*)d_in[1];
    const int*   ei     = (const int*)  d_in[2];
    const int*   src    = ei;
    const int*   dst    = ei + NE;
    const float* emb_W1 = (const float*)d_in[3];
    const float* emb_b1 = (const float*)d_in[4];
    const float* emb_g1 = (const float*)d_in[5];
    const float* emb_be1= (const float*)d_in[6];
    const float* emb_W2 = (const float*)d_in[7];
    const float* emb_b2 = (const float*)d_in[8];
    const float* emb_g2 = (const float*)d_in[9];
    const float* emb_be2= (const float*)d_in[10];
    const float* m1W    = (const float*)d_in[11];
    const float* m1b    = (const float*)d_in[12];
    const float* m2W    = (const float*)d_in[13];
    const float* m2b    = (const float*)d_in[14];
    const float* u1W    = (const float*)d_in[15];
    const float* u1b    = (const float*)d_in[16];
    const float* u2W    = (const float*)d_in[17];
    const float* u2b    = (const float*)d_in[18];
    const float* bng    = (const float*)d_in[19];
    const float* bnb    = (const float*)d_in[20];
    const float* c1W    = (const float*)d_in[21];
    const float* c1b    = (const float*)d_in[22];
    const float* c2W    = (const float*)d_in[23];
    const float* c2b    = (const float*)d_in[24];
    const float* c3W    = (const float*)d_in[25];
    const float* c3b    = (const float*)d_in[26];
    float* out = (float*)d_out;

    float *p_hn, *p_up, *p_agg, *p_Pd, *p_Ps;
    char *p_img;
    cudaGetSymbolAddress((void**)&p_hn,   g_hn);
    cudaGetSymbolAddress((void**)&p_up,   g_up);
    cudaGetSymbolAddress((void**)&p_agg,  g_agg);
    cudaGetSymbolAddress((void**)&p_Pd,   g_Pd);
    cudaGetSymbolAddress((void**)&p_Ps,   g_Ps);
    cudaGetSymbolAddress((void**)&p_img,  g_Bimg);

    cudaFuncSetAttribute(gemm_edge, cudaFuncAttributeMaxDynamicSharedMemorySize, FO::TOT);
    cudaFuncSetAttribute(gemm_pdps, cudaFuncAttributeMaxDynamicSharedMemorySize, PO::TOT);
    cudaFuncSetAttribute(gemm_emb,  cudaFuncAttributeMaxDynamicSharedMemorySize, EO_SMEM);
    cudaFuncSetAttribute(gemm_u1,   cudaFuncAttributeMaxDynamicSharedMemorySize, U1O::TOT);
    cudaFuncSetAttribute(gemm_u2,   cudaFuncAttributeMaxDynamicSharedMemorySize, U2O::TOT);

    const int NB  = (NN + SBK - 1) / SBK;
    const int GO  = 296;   // 2-CTA/SM grids
    const int GF  = 304;
    const int GP  = 152;   // pdps (1 CTA/SM)

    auto chunk = [&](int idx) -> char* { return p_img + (size_t)idx * 65536; };

    // ---- prep ALL weight images in one launch ----
    k_prepB_all<<<(NCHUNK_TOT*16384+255)/256,256>>>(emb_W2, m1W, m2W, u1W, u2W, p_img);

    // ---- preprocessing ----
    k_pre<<<(NN+255)/256,256>>>(pos);
    k_hist<<<(NE+255)/256,256>>>(dst);
    k_scanA<<<NB,SBK>>>();
    k_scanB<<<1,128>>>(NB);
    k_scanC<<<(NN+255)/256,256>>>();
    k_scatter<<<(NE+255)/256,256>>>(u, pos, src, dst);

    // ---- embedding (BN1 fin fused into stats; BN2 fin fused into emb GEMM) ----
    k_h0<<<(NN*HH+255)/256,256>>>(u, pos, emb_W1, emb_b1);
    k_bn_stats<<<(NN+255)/256,128>>>(p_hn, emb_g1, emb_be1);
    gemm_emb<<<GO,256,EO_SMEM>>>(p_hn, chunk(0), emb_b2, p_hn, NN, emb_g2, emb_be2);

    // ---- message-passing layers ----
    for (int i = 0; i < LL; i++){
        const float* Wt = m1W + (size_t)i*260*128 + 256*128;
        const float* wv = u1W + (size_t)i*257*128 + 256*128;   // rank-1 var row of u1_W
        gemm_pdps<<<GP,256,PO::TOT>>>(chunk(1+i*7+0), chunk(1+i*7+1),
                                      m1b + i*128, p_Pd, p_Ps, NN);
        gemm_edge<<<GF,256,FO::TOT>>>(chunk(1+i*7+2), m2b + i*128, p_agg, Wt, NE);
        gemm_u1<<<GO,256,U1O::TOT>>>(chunk(1+i*7+3), u1b + i*128, wv, p_up, NN);
        gemm_u2<<<GO,256,U2O::TOT>>>(p_up, chunk(1+i*7+6), u2b + i*128, p_hn, NN,
                                     bng + i*128, bnb + i*128);
    }

    // ---- CNN head ----
    k_cnn<<<(NN+63)/64,64>>>(c1W, c1b, c2W, c2b, c3W, c3b, out);
}

// round 17
// speedup vs baseline: 1.0491x; 1.0319x over previous
#include <cuda_runtime.h>
#include <cuda_fp16.h>
#include <cstdint>

#define NN 50000
#define NE 600000
#define HH 128
#define LL 6

typedef unsigned long long u64;
typedef unsigned int u32;

// ---------------- scratch (static device buffers; no allocation) ----------------
__device__ float g_hn [NN*HH];      // raw pre-BN node tensor "n"
__device__ float g_up [NN*HH];
__device__ float g_agg[NN*HH];
__device__ float g_Pd [NN*HH];
__device__ float g_Ps [NN*HH];
__device__ float4 g_tl[NE];
__device__ int   g_sdst[NE];
__device__ int   g_ssrc[NE];
__device__ int   g_cnt[NN];
__device__ int   g_woff[NN];
__device__ int   g_bsum[128];
__device__ float g_invdeg[NN];
__device__ float g_var[NN];
__device__ float g_sum[HH];         // zero-init; every fin re-zeros (invariant)
__device__ float g_sumsq[HH];
__device__ float g_ba[HH];
__device__ float g_bc[HH];
__device__ int   g_tick;            // last-CTA ticket; zero-init; every fin re-zeros
#define NCHUNK_TOT 43
__device__ char g_Bimg[(size_t)NCHUNK_TOT * 65536];   // fp16 hi-limb [n][k], 32KB used/chunk

// ---------------- PTX helpers ----------------
__device__ __forceinline__ u32 smem_u32(const void* p){
    u32 a; asm("{ .reg .u64 t; cvta.to.shared.u64 t, %1; cvt.u32.u64 %0, t; }" : "=r"(a) : "l"(p));
    return a;
}
__device__ __forceinline__ void ldsm4(u32 &r0, u32 &r1, u32 &r2, u32 &r3, u32 addr){
    asm volatile("ldmatrix.sync.aligned.m8n8.x4.shared.b16 {%0,%1,%2,%3}, [%4];"
        : "=r"(r0), "=r"(r1), "=r"(r2), "=r"(r3) : "r"(addr));
}
__device__ __forceinline__ void mma16816(float4 &d, const u32* a, u32 b0, u32 b1){
    asm volatile("mma.sync.aligned.m16n8k16.row.col.f32.f16.f16.f32 "
        "{%0,%1,%2,%3}, {%4,%5,%6,%7}, {%8,%9}, {%0,%1,%2,%3};"
        : "+f"(d.x), "+f"(d.y), "+f"(d.z), "+f"(d.w)
        : "r"(a[0]), "r"(a[1]), "r"(a[2]), "r"(a[3]), "r"(b0), "r"(b1));
}
__device__ __forceinline__ u32 pack_h2(float v0, float v1){
    u32 r; asm("cvt.rn.f16x2.f32 %0, %1, %2;" : "=r"(r) : "f"(v1), "f"(v0)); return r;
}
__device__ __forceinline__ float trunc_hi(float v){
    return __uint_as_float(__float_as_uint(v) & 0xFFFFE000u);
}
__device__ __forceinline__ void split8(const float* v, u32* hw, u32* lw){
    #pragma unroll
    for (int q = 0; q < 4; q++){
        float h0 = trunc_hi(v[2*q]);
        float h1 = trunc_hi(v[2*q+1]);
        hw[q] = pack_h2(h0, h1);
        lw[q] = pack_h2(v[2*q] - h0, v[2*q+1] - h1);
    }
}

// BN fin: compute affine from stats, re-zero stats. Call with tid<128 active.
__device__ __forceinline__ void bn_fin_dev(int tid, const float* __restrict__ g,
                                           const float* __restrict__ be){
    if (tid < 128){
        float mu  = g_sum[tid]   * (1.f/NN);
        float var = g_sumsq[tid] * (1.f/NN) - mu*mu;
        float a = g[tid] * rsqrtf(var + 1e-5f);
        g_ba[tid] = a;
        g_bc[tid] = be[tid] - a*mu;
        g_sum[tid] = 0.f;
        g_sumsq[tid] = 0.f;
    }
}

// ======================================================================
// EDGE kernel (scatter GEMM), 2 CTAs/SM. Proven R13 (pure atomics).
// ======================================================================
struct FO {
    static constexpr int B0 = 40960;
    static constexpr int WT = B0 + 34816;
    static constexpr int I0 = WT + 2048;
    static constexpr int I1 = I0 + 512;
    static constexpr int TL = I1 + 512;
    static constexpr int BI = TL + 2048;
    static constexpr int TOT = BI + 512;
};

struct Pref1 { float4 x0, x1, y0, y1; };

__device__ __forceinline__ void edge_ldg(int i0, int i1, int kglob, Pref1& p){
    p.x0 = *(const float4*)&g_Pd[(size_t)i0*HH + kglob];
    p.x1 = *(const float4*)&g_Pd[(size_t)i0*HH + kglob + 4];
    p.y0 = *(const float4*)&g_Ps[(size_t)i1*HH + kglob];
    p.y1 = *(const float4*)&g_Ps[(size_t)i1*HH + kglob + 4];
}
__device__ __forceinline__ void edge_fin(const Pref1& p, int row, int kglob,
    const float* __restrict__ s_wt, const float4* __restrict__ s_tl, float* v)
{
    v[0]=p.x0.x+p.y0.x; v[1]=p.x0.y+p.y0.y; v[2]=p.x0.z+p.y0.z; v[3]=p.x0.w+p.y0.w;
    v[4]=p.x1.x+p.y1.x; v[5]=p.x1.y+p.y1.y; v[6]=p.x1.z+p.y1.z; v[7]=p.x1.w+p.y1.w;
    float4 tl = s_tl[row];
    #pragma unroll
    for (int t = 0; t < 4; t++){
        float tv = (&tl.x)[t];
        const float* wr = &s_wt[t*HH + kglob];
        #pragma unroll
        for (int kk = 0; kk < 8; kk++) v[kk] += tv * wr[kk];
    }
    #pragma unroll
    for (int kk = 0; kk < 8; kk++) v[kk] = fmaxf(v[kk], 0.f);
}

__device__ __forceinline__ void cvt_store(const float* v, char* smem, u32 aoff){
    u32 hw[4], lw[4];
    split8(v, hw, lw);
    *(uint4*)(smem + aoff)         = make_uint4(hw[0],hw[1],hw[2],hw[3]);
    *(uint4*)(smem + 10240 + aoff) = make_uint4(lw[0],lw[1],lw[2],lw[3]);
}

__global__ __launch_bounds__(256, 2)
void gemm_edge(const char* __restrict__ Bimg, const float* __restrict__ bias,
               float* __restrict__ out, const float* __restrict__ Wt, int rows)
{
    extern __shared__ __align__(16) char smem[];
    const u32 sb  = smem_u32(smem);
    const int tid = threadIdx.x;
    const int wid = tid >> 5;
    const int lane = tid & 31;

    int*    s_i0 = (int*)   (smem + FO::I0);
    int*    s_i1 = (int*)   (smem + FO::I1);
    float4* s_tl = (float4*)(smem + FO::TL);
    float*  s_bi = (float*) (smem + FO::BI);
    float*  s_wt = (float*) (smem + FO::WT);
    __shared__ int s_nh;
    __shared__ int s_hd[64];

    {
        const uint4* bsrc = (const uint4*)Bimg;
        for (int i = tid; i < 2048; i += 256){
            int row = i >> 4, cc = i & 15;
            *(uint4*)(smem + FO::B0 + row*272 + cc*16) = bsrc[i];
        }
    }
    for (int i = tid; i < 4*HH; i += 256) s_wt[i] = Wt[i];
    if (tid < 128) s_bi[tid] = bias[tid];

    const int warp_m = wid & 3;
    const int warp_n = wid >> 2;
    const int qi = lane & 7, qd = lane >> 3;
    const u32 a_rd = (u32)((warp_m*32 + (qd&1)*8 + qi)*80 + (qd>>1)*16);
    const u32 b_rd = sb + FO::B0 + (u32)((warp_n*64 + (qd>>1)*8 + qi)*272 + (qd&1)*16);

    for (int base = blockIdx.x * 128; base < rows; base += gridDim.x * 128){
        __syncthreads();
        if (tid < 128){
            int r = base + tid;
            bool v = r < rows;
            s_i0[tid] = v ? g_sdst[r] : 0;
            s_i1[tid] = v ? g_ssrc[r] : 0;
            s_tl[tid] = v ? g_tl[r]   : make_float4(0.f,0.f,0.f,0.f);
        }
        __syncthreads();

        float4 acc[2][8];
        #pragma unroll
        for (int i=0;i<2;i++)
            #pragma unroll
            for (int j=0;j<8;j++) acc[i][j] = make_float4(0.f,0.f,0.f,0.f);

        Pref1 pf[2];
        int it_row[2], it_k0l[2], it_i0[2], it_i1[2];
        #pragma unroll
        for (int it = 0; it < 2; it++){
            int g = tid + it*256;
            it_row[it] = g >> 2;
            it_k0l[it] = (g & 3) * 8;
            it_i0[it] = s_i0[it_row[it]];
            it_i1[it] = s_i1[it_row[it]];
        }

        #pragma unroll
        for (int it = 0; it < 2; it++)
            edge_ldg(it_i0[it], it_i1[it], it_k0l[it], pf[it]);
        #pragma unroll
        for (int it = 0; it < 2; it++){
            float v[8];
            edge_fin(pf[it], it_row[it], it_k0l[it], s_wt, s_tl, v);
            cvt_store(v, smem, (u32)(it_row[it]*80 + it_k0l[it]*2));
        }
        __syncthreads();

        #pragma unroll
        for (int s = 0; s < 4; s++){
            if (s + 1 < 4){
                #pragma unroll
                for (int it = 0; it < 2; it++)
                    edge_ldg(it_i0[it], it_i1[it], (s+1)*32 + it_k0l[it], pf[it]);
            }
            {
                u32 abuf = sb + (u32)((s & 1) * 20480) + a_rd;
                #pragma unroll
                for (int ka = 0; ka < 2; ka++){
                    u32 ah[2][4], al[2][4];
                    u32 ab = abuf + ka*32;
                    ldsm4(ah[0][0],ah[0][1],ah[0][2],ah[0][3], ab);
                    ldsm4(ah[1][0],ah[1][1],ah[1][2],ah[1][3], ab + 1280);
                    ldsm4(al[0][0],al[0][1],al[0][2],al[0][3], ab + 10240);
                    ldsm4(al[1][0],al[1][1],al[1][2],al[1][3], ab + 11520);
                    u32 bb0 = b_rd + (u32)((s*32 + ka*16) * 2);
                    #pragma unroll
                    for (int p = 0; p < 4; p++){
                        u32 h0,h1,h2,h3;
                        ldsm4(h0,h1,h2,h3, bb0 + p*4352);
                        #pragma unroll
                        for (int am = 0; am < 2; am++){
                            mma16816(acc[am][2*p],   ah[am], h0, h1);
                            mma16816(acc[am][2*p],   al[am], h0, h1);
                            mma16816(acc[am][2*p+1], ah[am], h2, h3);
                            mma16816(acc[am][2*p+1], al[am], h2, h3);
                        }
                    }
                }
            }
            if (s + 1 < 4){
                #pragma unroll
                for (int it = 0; it < 2; it++){
                    float v[8];
                    edge_fin(pf[it], it_row[it], (s+1)*32 + it_k0l[it], s_wt, s_tl, v);
                    cvt_store(v, smem, (u32)(((s+1)&1)*20480 + it_row[it]*80 + it_k0l[it]*2));
                }
            }
            __syncthreads();
        }

        // scatter: two 64-row phases staged in the A region (R13 proven)
        float* s_red = (float*)smem;   // 64 x 132 floats
        #pragma unroll
        for (int phase = 0; phase < 2; phase++){
            if ((warp_m >> 1) == phase){
                #pragma unroll
                for (int am = 0; am < 2; am++)
                    #pragma unroll
                    for (int na = 0; na < 8; na++){
                        int ml = (warp_m & 1)*32 + am*16 + (lane >> 2);
                        int n0 = warp_n*64 + na*8 + (lane & 3)*2;
                        float b0 = s_bi[n0], b1 = s_bi[n0+1];
                        float4 c = acc[am][na];
                        s_red[ml*132 + n0]       = fmaxf(c.x + b0, 0.f);
                        s_red[ml*132 + n0 + 1]   = fmaxf(c.y + b1, 0.f);
                        s_red[(ml+8)*132 + n0]   = fmaxf(c.z + b0, 0.f);
                        s_red[(ml+8)*132 + n0+1] = fmaxf(c.w + b1, 0.f);
                    }
            }
            if (tid == 0) s_nh = 0;
            __syncthreads();
            if (tid < 64){
                int li = phase*64 + tid;
                int r = base + li;
                if (r < rows){
                    bool head = (tid == 0) || (s_i0[li] != s_i0[li-1]);
                    if (head){ int p = atomicAdd(&s_nh, 1); s_hd[p] = tid; }
                }
            }
            __syncthreads();
            int nh = s_nh;
            for (int item = tid; item < nh*32; item += 256){
                int h = s_hd[item >> 5];
                int strip = (item & 31) * 4;
                int d = s_i0[phase*64 + h];
                float a0=0.f, a1=0.f, a2=0.f, a3=0.f;
                int rr = h;
                while (rr < 64 && (base + phase*64 + rr) < rows && s_i0[phase*64 + rr] == d){
                    float* rp = &s_red[rr*132 + strip];
                    a0 += rp[0]; a1 += rp[1]; a2 += rp[2]; a3 += rp[3];
                    rr++;
                }
                atomicAdd(&out[(size_t)d*HH + strip + 0], a0);
                atomicAdd(&out[(size_t)d*HH + strip + 1], a1);
                atomicAdd(&out[(size_t)d*HH + strip + 2], a2);
                atomicAdd(&out[(size_t)d*HH + strip + 3], a3);
            }
            __syncthreads();
        }
    }
}

// ======================================================================
// FUSED Pd+Ps kernel (1 CTA/SM). Proven R10/R12/R13.
// ======================================================================
struct PO {
    static constexpr int B0 = 81920;
    static constexpr int B1 = 116736;
    static constexpr int BA = 151552;
    static constexpr int BC = BA + 512;
    static constexpr int BI = BC + 512;
    static constexpr int TOT = BI + 512;
};

__global__ __launch_bounds__(256, 1)
void gemm_pdps(const char* __restrict__ Bimg0, const char* __restrict__ Bimg1,
               const float* __restrict__ bias0,
               float* __restrict__ out0, float* __restrict__ out1, int rows)
{
    extern __shared__ __align__(16) char smem[];
    const u32 sb  = smem_u32(smem);
    const int tid = threadIdx.x;
    const int wid = tid >> 5;
    const int lane = tid & 31;

    float* s_ba = (float*)(smem + PO::BA);
    float* s_bc = (float*)(smem + PO::BC);
    float* s_bi = (float*)(smem + PO::BI);

    {
        const uint4* b0 = (const uint4*)Bimg0;
        const uint4* b1 = (const uint4*)Bimg1;
        for (int i = tid; i < 2048; i += 256){
            int row = i >> 4, cc = i & 15;
            *(uint4*)(smem + PO::B0 + row*272 + cc*16) = b0[i];
            *(uint4*)(smem + PO::B1 + row*272 + cc*16) = b1[i];
        }
    }
    if (tid < 128){
        s_ba[tid] = g_ba[tid];
        s_bc[tid] = g_bc[tid];
        s_bi[tid] = bias0[tid];
    }

    const int warp_m = wid & 3;
    const int warp_n = wid >> 2;
    const int qi = lane & 7, qd = lane >> 3;
    const u32 a_rd  = (u32)((warp_m*32 + (qd&1)*8 + qi)*80 + (qd>>1)*16);
    const u32 b_off = (u32)((warp_n*64 + (qd>>1)*8 + qi)*272 + (qd&1)*16);

    for (int base = blockIdx.x * 128; base < rows; base += gridDim.x * 128){
        __syncthreads();

        #pragma unroll
        for (int it = 0; it < 2; it++){
            int g = tid + it*256;
            int row = g >> 2;
            int k0l = (g & 3) * 8;
            int arow = min(base + row, rows - 1);
            #pragma unroll
            for (int s = 0; s < 4; s++){
                int kg = s*32 + k0l;
                float4 a0 = *(const float4*)&g_hn[(size_t)arow*HH + kg];
                float4 a1 = *(const float4*)&g_hn[(size_t)arow*HH + kg + 4];
                float v[8] = {a0.x,a0.y,a0.z,a0.w,a1.x,a1.y,a1.z,a1.w};
                #pragma unroll
                for (int kk = 0; kk < 8; kk++)
                    v[kk] = s_ba[kg+kk]*v[kk] + s_bc[kg+kk];
                cvt_store(v, smem, (u32)(s*20480 + row*80 + k0l*2));
            }
        }
        __syncthreads();

        #pragma unroll
        for (int pass = 0; pass < 2; pass++){
            const u32 b_rd = sb + (pass ? PO::B1 : PO::B0) + b_off;
            float4 acc[2][8];
            #pragma unroll
            for (int i=0;i<2;i++)
                #pragma unroll
                for (int j=0;j<8;j++) acc[i][j] = make_float4(0.f,0.f,0.f,0.f);

            #pragma unroll
            for (int s = 0; s < 4; s++){
                u32 abuf = sb + (u32)(s * 20480) + a_rd;
                #pragma unroll
                for (int ka = 0; ka < 2; ka++){
                    u32 ah[2][4], al[2][4];
                    u32 ab = abuf + ka*32;
                    ldsm4(ah[0][0],ah[0][1],ah[0][2],ah[0][3], ab);
                    ldsm4(ah[1][0],ah[1][1],ah[1][2],ah[1][3], ab + 1280);
                    ldsm4(al[0][0],al[0][1],al[0][2],al[0][3], ab + 10240);
                    ldsm4(al[1][0],al[1][1],al[1][2],al[1][3], ab + 11520);
                    u32 bb0 = b_rd + (u32)((s*32 + ka*16) * 2);
                    #pragma unroll
                    for (int p = 0; p < 4; p++){
                        u32 h0,h1,h2,h3;
                        ldsm4(h0,h1,h2,h3, bb0 + p*4352);
                        #pragma unroll
                        for (int am = 0; am < 2; am++){
                            mma16816(acc[am][2*p],   ah[am], h0, h1);
                            mma16816(acc[am][2*p],   al[am], h0, h1);
                            mma16816(acc[am][2*p+1], ah[am], h2, h3);
                            mma16816(acc[am][2*p+1], al[am], h2, h3);
                        }
                    }
                }
            }

            float* outp = pass ? out1 : out0;
            #pragma unroll
            for (int am = 0; am < 2; am++)
                #pragma unroll
                for (int na = 0; na < 8; na++){
                    int m0 = warp_m*32 + am*16 + (lane >> 2);
                    int n0 = warp_n*64 + na*8 + (lane & 3)*2;
                    float b0 = pass ? 0.f : s_bi[n0];
                    float b1 = pass ? 0.f : s_bi[n0+1];
                    float4 c = acc[am][na];
                    int r0 = base + m0;
                    if (r0 < rows){
                        *(float2*)&outp[(size_t)r0*HH + n0] = make_float2(c.x + b0, c.y + b1);
                        if (pass) *(float2*)&g_agg[(size_t)r0*HH + n0] = make_float2(0.f, 0.f);
                    }
                    if (r0 + 8 < rows){
                        *(float2*)&outp[(size_t)(r0+8)*HH + n0] = make_float2(c.z + b0, c.w + b1);
                        if (pass) *(float2*)&g_agg[(size_t)(r0+8)*HH + n0] = make_float2(0.f, 0.f);
                    }
                }
        }
    }
}

// ======================================================================
// u1 kernel: K=256, both B chunks resident, DOUBLE-BUFFERED A with LDG
// prefetch (edge-style, 1 sync/sub), direct-register epilogue. 2 CTAs/SM.
// A buf0 [0,20480), buf1 [20480,40960). B chunks at 40960 + c*34816.
// ======================================================================
struct U1O {
    static constexpr int B0  = 40960;
    static constexpr int F0  = 110592;
    static constexpr int F1  = F0 + 512;
    static constexpr int BA  = F1 + 512;
    static constexpr int BC  = BA + 512;
    static constexpr int B1O = BC + 512;
    static constexpr int WV  = B1O + 512;
    static constexpr int TOT = WV + 512;   // 113664
};

__global__ __launch_bounds__(256, 2)
void gemm_u1(const char* __restrict__ Bimg, const float* __restrict__ b1,
             const float* __restrict__ wv, float* __restrict__ out, int rows)
{
    extern __shared__ __align__(16) char smem[];
    const u32 sb  = smem_u32(smem);
    const int tid = threadIdx.x;
    const int wid = tid >> 5;
    const int lane = tid & 31;

    float* s_f0 = (float*)(smem + U1O::F0);
    float* s_f1 = (float*)(smem + U1O::F1);
    float* s_ba = (float*)(smem + U1O::BA);
    float* s_bc = (float*)(smem + U1O::BC);
    float* s_b1 = (float*)(smem + U1O::B1O);
    float* s_wv = (float*)(smem + U1O::WV);

    // one-time: both B chunks + constants
    #pragma unroll
    for (int c = 0; c < 2; c++){
        const uint4* bsrc = (const uint4*)(Bimg + (size_t)c * 65536);
        for (int i = tid; i < 2048; i += 256){
            int row = i >> 4, cc = i & 15;
            *(uint4*)(smem + U1O::B0 + c*34816 + row*272 + cc*16) = bsrc[i];
        }
    }
    if (tid < 128){
        s_ba[tid] = g_ba[tid]; s_bc[tid] = g_bc[tid];
        s_b1[tid] = b1[tid];   s_wv[tid] = wv[tid];
    }

    const int warp_m = wid & 3;
    const int warp_n = wid >> 2;
    const int qi = lane & 7, qd = lane >> 3;
    const u32 a_rd = (u32)((warp_m*32 + (qd&1)*8 + qi)*80 + (qd>>1)*16);
    const u32 b_rd = sb + U1O::B0 + (u32)((warp_n*64 + (qd>>1)*8 + qi)*272 + (qd&1)*16);

    for (int base = blockIdx.x * 128; base < rows; base += gridDim.x * 128){
        __syncthreads();   // prev epilogue (reads s_f1) done; covers one-time loads
        if (tid < 128){
            int rc = min(base + tid, rows - 1);
            s_f0[tid] = g_invdeg[rc];
            s_f1[tid] = g_var[rc];
        }
        __syncthreads();

        float4 acc[2][8];
        #pragma unroll
        for (int i=0;i<2;i++)
            #pragma unroll
            for (int j=0;j<8;j++) acc[i][j] = make_float4(0.f,0.f,0.f,0.f);

        int it_row[2], it_k0l[2], it_arow[2];
        #pragma unroll
        for (int it = 0; it < 2; it++){
            int g = tid + it*256;
            it_row[it]  = g >> 2;
            it_k0l[it]  = (g & 3) * 8;
            it_arow[it] = min(base + it_row[it], rows - 1);
        }

        float4 pfa[2], pfb[2];
        // prologue: prefetch + store sub 0 (g_hn, affine)
        #pragma unroll
        for (int it = 0; it < 2; it++){
            pfa[it] = *(const float4*)&g_hn[(size_t)it_arow[it]*HH + it_k0l[it]];
            pfb[it] = *(const float4*)&g_hn[(size_t)it_arow[it]*HH + it_k0l[it] + 4];
        }
        #pragma unroll
        for (int it = 0; it < 2; it++){
            int kg = it_k0l[it];
            float v[8] = {pfa[it].x,pfa[it].y,pfa[it].z,pfa[it].w,
                          pfb[it].x,pfb[it].y,pfb[it].z,pfb[it].w};
            #pragma unroll
            for (int kk = 0; kk < 8; kk++)
                v[kk] = s_ba[kg+kk]*v[kk] + s_bc[kg+kk];
            cvt_store(v, smem, (u32)(it_row[it]*80 + it_k0l[it]*2));
        }
        __syncthreads();

        #pragma unroll
        for (int s = 0; s < 8; s++){
            // prefetch next sub's gathers
            if (s + 1 < 8){
                int kb = (s+1)*32;
                #pragma unroll
                for (int it = 0; it < 2; it++){
                    if (s + 1 < 4){
                        pfa[it] = *(const float4*)&g_hn[(size_t)it_arow[it]*HH + kb + it_k0l[it]];
                        pfb[it] = *(const float4*)&g_hn[(size_t)it_arow[it]*HH + kb + it_k0l[it] + 4];
                    } else {
                        pfa[it] = *(const float4*)&g_agg[(size_t)it_arow[it]*HH + (kb-128) + it_k0l[it]];
                        pfb[it] = *(const float4*)&g_agg[(size_t)it_arow[it]*HH + (kb-128) + it_k0l[it] + 4];
                    }
                }
            }
            // compute from buf[s&1]
            {
                u32 abuf = sb + (u32)((s & 1) * 20480) + a_rd;
                u32 bchunk = b_rd + (u32)((s >> 2) * 34816);
                #pragma unroll
                for (int ka = 0; ka < 2; ka++){
                    u32 ah[2][4], al[2][4];
                    u32 ab = abuf + ka*32;
                    ldsm4(ah[0][0],ah[0][1],ah[0][2],ah[0][3], ab);
                    ldsm4(ah[1][0],ah[1][1],ah[1][2],ah[1][3], ab + 1280);
                    ldsm4(al[0][0],al[0][1],al[0][2],al[0][3], ab + 10240);
                    ldsm4(al[1][0],al[1][1],al[1][2],al[1][3], ab + 11520);
                    u32 bb0 = bchunk + (u32)(((s & 3)*32 + ka*16) * 2);
                    #pragma unroll
                    for (int p = 0; p < 4; p++){
                        u32 h0,h1,h2,h3;
                        ldsm4(h0,h1,h2,h3, bb0 + p*4352);
                        #pragma unroll
                        for (int am = 0; am < 2; am++){
                            mma16816(acc[am][2*p],   ah[am], h0, h1);
                            mma16816(acc[am][2*p],   al[am], h0, h1);
                            mma16816(acc[am][2*p+1], ah[am], h2, h3);
                            mma16816(acc[am][2*p+1], al[am], h2, h3);
                        }
                    }
                }
            }
            // finalize + store next sub into the other buffer
            if (s + 1 < 8){
                int kb = (s+1)*32;
                #pragma unroll
                for (int it = 0; it < 2; it++){
                    float v[8] = {pfa[it].x,pfa[it].y,pfa[it].z,pfa[it].w,
                                  pfb[it].x,pfb[it].y,pfb[it].z,pfb[it].w};
                    if (s + 1 < 4){
                        int kg = kb + it_k0l[it];
                        #pragma unroll
                        for (int kk = 0; kk < 8; kk++)
                            v[kk] = s_ba[kg+kk]*v[kk] + s_bc[kg+kk];
                    } else {
                        float invd = s_f0[it_row[it]];
                        #pragma unroll
                        for (int kk = 0; kk < 8; kk++) v[kk] *= invd;
                    }
                    cvt_store(v, smem, (u32)(((s+1)&1)*20480 + it_row[it]*80 + it_k0l[it]*2));
                }
            }
            __syncthreads();
        }

        // ---- direct-register epilogue: relu(acc + b1 + var*wv) -> out ----
        #pragma unroll
        for (int am = 0; am < 2; am++)
            #pragma unroll
            for (int na = 0; na < 8; na++){
                int m0 = warp_m*32 + am*16 + (lane >> 2);
                int n0 = warp_n*64 + na*8 + (lane & 3)*2;
                float4 c = acc[am][na];
                float bb0 = s_b1[n0], bb1 = s_b1[n0+1];
                float w0 = s_wv[n0],  w1 = s_wv[n0+1];
                float f1a = s_f1[m0], f1b = s_f1[m0+8];
                float v0 = fmaxf(c.x + bb0 + f1a*w0, 0.f);
                float v1 = fmaxf(c.y + bb1 + f1a*w1, 0.f);
                float v2 = fmaxf(c.z + bb0 + f1b*w0, 0.f);
                float v3 = fmaxf(c.w + bb1 + f1b*w1, 0.f);
                int r0 = base + m0;
                if (r0 < rows)     *(float2*)&out[(size_t)r0*HH + n0]     = make_float2(v0,v1);
                if (r0 + 8 < rows) *(float2*)&out[(size_t)(r0+8)*HH + n0] = make_float2(v2,v3);
            }
    }
}

// ======================================================================
// u2 kernel: K=128, B resident above staging; DOUBLE-BUFFERED A with LDG
// prefetch (1 sync/sub); resid + stats + fused BN fin. 2 CTAs/SM.
// A buf0 [0,20480), buf1 [20480,40960); s_red [0,67584); B at 67584.
// ======================================================================
struct U2O {
    static constexpr int B  = 67584;
    static constexpr int BA = 102400;
    static constexpr int BC = BA + 512;
    static constexpr int TOT = BC + 512;
};

__global__ __launch_bounds__(256, 2)
void gemm_u2(const float* __restrict__ A, const char* __restrict__ Bimg,
             const float* __restrict__ bias, float* __restrict__ out, int rows,
             const float* __restrict__ fg, const float* __restrict__ fb)
{
    extern __shared__ __align__(16) char smem[];
    const u32 sb  = smem_u32(smem);
    const int tid = threadIdx.x;
    const int wid = tid >> 5;
    const int lane = tid & 31;

    float* s_ba = (float*)(smem + U2O::BA);
    float* s_bc = (float*)(smem + U2O::BC);

    {
        const uint4* bsrc = (const uint4*)Bimg;
        for (int i = tid; i < 2048; i += 256){
            int row = i >> 4, cc = i & 15;
            *(uint4*)(smem + U2O::B + row*272 + cc*16) = bsrc[i];
        }
    }
    if (tid < 128){
        s_ba[tid] = g_ba[tid];
        s_bc[tid] = g_bc[tid];
    }

    const int warp_m = wid & 3;
    const int warp_n = wid >> 2;
    const int qi = lane & 7, qd = lane >> 3;
    const u32 a_rd = (u32)((warp_m*32 + (qd&1)*8 + qi)*80 + (qd>>1)*16);
    const u32 b_rd = sb + U2O::B + (u32)((warp_n*64 + (qd>>1)*8 + qi)*272 + (qd&1)*16);

    for (int base = blockIdx.x * 128; base < rows; base += gridDim.x * 128){
        __syncthreads();   // prev epilogue done (s_red/A safe); covers one-time loads

        float4 acc[2][8];
        #pragma unroll
        for (int i=0;i<2;i++)
            #pragma unroll
            for (int j=0;j<8;j++) acc[i][j] = make_float4(0.f,0.f,0.f,0.f);

        int it_row[2], it_k0l[2], it_arow[2];
        #pragma unroll
        for (int it = 0; it < 2; it++){
            int g = tid + it*256;
            it_row[it]  = g >> 2;
            it_k0l[it]  = (g & 3) * 8;
            it_arow[it] = min(base + it_row[it], rows - 1);
        }

        float4 pfa[2], pfb[2];
        // prologue: prefetch + store sub 0 (plain)
        #pragma unroll
        for (int it = 0; it < 2; it++){
            pfa[it] = *(const float4*)&A[(size_t)it_arow[it]*128 + it_k0l[it]];
            pfb[it] = *(const float4*)&A[(size_t)it_arow[it]*128 + it_k0l[it] + 4];
        }
        #pragma unroll
        for (int it = 0; it < 2; it++){
            float v[8] = {pfa[it].x,pfa[it].y,pfa[it].z,pfa[it].w,
                          pfb[it].x,pfb[it].y,pfb[it].z,pfb[it].w};
            cvt_store(v, smem, (u32)(it_row[it]*80 + it_k0l[it]*2));
        }
        __syncthreads();

        #pragma unroll
        for (int s = 0; s < 4; s++){
            if (s + 1 < 4){
                int kb = (s+1)*32;
                #pragma unroll
                for (int it = 0; it < 2; it++){
                    pfa[it] = *(const float4*)&A[(size_t)it_arow[it]*128 + kb + it_k0l[it]];
                    pfb[it] = *(const float4*)&A[(size_t)it_arow[it]*128 + kb + it_k0l[it] + 4];
                }
            }
            {
                u32 abuf = sb + (u32)((s & 1) * 20480) + a_rd;
                #pragma unroll
                for (int ka = 0; ka < 2; ka++){
                    u32 ah[2][4], al[2][4];
                    u32 ab = abuf + ka*32;
                    ldsm4(ah[0][0],ah[0][1],ah[0][2],ah[0][3], ab);
                    ldsm4(ah[1][0],ah[1][1],ah[1][2],ah[1][3], ab + 1280);
                    ldsm4(al[0][0],al[0][1],al[0][2],al[0][3], ab + 10240);
                    ldsm4(al[1][0],al[1][1],al[1][2],al[1][3], ab + 11520);
                    u32 bb0 = b_rd + (u32)((s*32 + ka*16) * 2);
                    #pragma unroll
                    for (int p = 0; p < 4; p++){
                        u32 h0,h1,h2,h3;
                        ldsm4(h0,h1,h2,h3, bb0 + p*4352);
                        #pragma unroll
                        for (int am = 0; am < 2; am++){
                            mma16816(acc[am][2*p],   ah[am], h0, h1);
                            mma16816(acc[am][2*p],   al[am], h0, h1);
                            mma16816(acc[am][2*p+1], ah[am], h2, h3);
                            mma16816(acc[am][2*p+1], al[am], h2, h3);
                        }
                    }
                }
            }
            if (s + 1 < 4){
                #pragma unroll
                for (int it = 0; it < 2; it++){
                    float v[8] = {pfa[it].x,pfa[it].y,pfa[it].z,pfa[it].w,
                                  pfb[it].x,pfb[it].y,pfb[it].z,pfb[it].w};
                    cvt_store(v, smem, (u32)(((s+1)&1)*20480 + it_row[it]*80 + it_k0l[it]*2));
                }
            }
            __syncthreads();
        }

        // staging epilogue (s_red at [0, 67584) — below resident B)
        float* s_red = (float*)smem;
        #pragma unroll
        for (int am = 0; am < 2; am++)
            #pragma unroll
            for (int na = 0; na < 8; na++){
                int m0 = warp_m*32 + am*16 + (lane >> 2);
                int n0 = warp_n*64 + na*8 + (lane & 3)*2;
                float4 c = acc[am][na];
                *(float2*)&s_red[m0*132 + n0]     = make_float2(c.x, c.y);
                *(float2*)&s_red[(m0+8)*132 + n0] = make_float2(c.z, c.w);
            }
        __syncthreads();

        for (int i = tid; i < 4096; i += 256){
            int row = i >> 5, c4 = (i & 31)*4;
            int r = base + row;
            if (r >= rows) continue;
            float4 v  = *(float4*)&s_red[row*132 + c4];
            float4 bb = *(const float4*)&bias[c4];
            v.x = fmaxf(v.x + bb.x, 0.f); v.y = fmaxf(v.y + bb.y, 0.f);
            v.z = fmaxf(v.z + bb.z, 0.f); v.w = fmaxf(v.w + bb.w, 0.f);
            float4 nv = *(const float4*)&out[(size_t)r*HH + c4];
            v.x += s_ba[c4+0]*nv.x + s_bc[c4+0];
            v.y += s_ba[c4+1]*nv.y + s_bc[c4+1];
            v.z += s_ba[c4+2]*nv.z + s_bc[c4+2];
            v.w += s_ba[c4+3]*nv.w + s_bc[c4+3];
            *(float4*)&out[(size_t)r*HH + c4] = v;
            *(float4*)&s_red[row*132 + c4] = v;
        }
        __syncthreads();
        {
            int nval = min(128, rows - base);
            if (tid < 128){
                float s = 0.f, s2 = 0.f;
                for (int rr = 0; rr < nval; rr++){
                    float v = s_red[rr*132 + tid];
                    s += v; s2 += v*v;
                }
                atomicAdd(&g_sum[tid], s);
                atomicAdd(&g_sumsq[tid], s2);
            }
        }
    }

    // fused BN fin for next layer
    __threadfence();
    __shared__ int s_rank;
    if (tid == 0) s_rank = atomicAdd(&g_tick, 1);
    __syncthreads();
    if (s_rank == (int)gridDim.x - 1){
        bn_fin_dev(tid, fg, fb);
        __threadfence();
        if (tid == 0) g_tick = 0;
    }
}

// ======================================================================
// Embedding GEMM, 2 CTAs/SM (R12 layout) + fused BN2 fin. Proven R13.
// ======================================================================
#define EO_A_HI   0
#define EO_A_LO   10240
#define EO_B_HI   36864
#define EO_BA     71680
#define EO_BC     72192
#define EO_SMEM   72704

__global__ __launch_bounds__(256, 2)
void gemm_emb(const float* __restrict__ A, const char* __restrict__ Bimg,
              const float* __restrict__ bias, float* __restrict__ out, int rows,
              const float* __restrict__ fg, const float* __restrict__ fb)
{
    extern __shared__ __align__(16) char smem[];
    const u32 sb  = smem_u32(smem);
    const int tid = threadIdx.x;
    const int wid = tid >> 5;
    const int lane = tid & 31;

    float*  s_ba = (float*) (smem + EO_BA);
    float*  s_bc = (float*) (smem + EO_BC);

    const int warp_m = wid & 3;
    const int warp_n = wid >> 2;
    const int qi = lane & 7, qd = lane >> 3;
    const u32 aab = sb + EO_A_HI + (u32)((warp_m*32 + (qd&1)*8 + qi)*80 + (qd>>1)*16);
    const u32 bab = sb + EO_B_HI + (u32)((warp_n*64 + (qd>>1)*8 + qi)*272 + (qd&1)*16);

    {
        const uint4* bsrc = (const uint4*)Bimg;
        for (int i = tid; i < 2048; i += 256){
            int row = i >> 4, c = i & 15;
            *(uint4*)(smem + EO_B_HI + row*272 + c*16) = bsrc[i];
        }
    }
    if (tid < 128){
        s_ba[tid] = g_ba[tid];
        s_bc[tid] = g_bc[tid];
    }

    for (int base = blockIdx.x * 128; base < rows; base += gridDim.x * 128){
        float4 acc[2][8];
        #pragma unroll
        for (int i=0;i<2;i++)
            #pragma unroll
            for (int j=0;j<8;j++) acc[i][j] = make_float4(0.f,0.f,0.f,0.f);

        for (int sub = 0; sub < 4; sub++){
            __syncthreads();
            #pragma unroll 1
            for (int g = tid; g < 512; g += 256){
                int row = g >> 2;
                int k0l = (g & 3) * 8;
                int kglob = sub*32 + k0l;
                int arow = min(base + row, rows - 1);
                float4 a0 = *(const float4*)&A[(size_t)arow*128 + kglob];
                float4 a1 = *(const float4*)&A[(size_t)arow*128 + kglob + 4];
                float v[8] = {a0.x,a0.y,a0.z,a0.w,a1.x,a1.y,a1.z,a1.w};
                #pragma unroll
                for (int kk = 0; kk < 8; kk++)
                    v[kk] = fmaxf(s_ba[kglob+kk]*v[kk] + s_bc[kglob+kk], 0.f);
                u32 hw[4], lw[4];
                split8(v, hw, lw);
                u32 aoff = (u32)(row*80 + k0l*2);
                *(uint4*)(smem + EO_A_HI + aoff) = make_uint4(hw[0],hw[1],hw[2],hw[3]);
                *(uint4*)(smem + EO_A_LO + aoff) = make_uint4(lw[0],lw[1],lw[2],lw[3]);
            }
            __syncthreads();
            #pragma unroll
            for (int ka = 0; ka < 2; ka++){
                u32 ah[2][4], al[2][4];
                u32 ab = aab + ka*32;
                ldsm4(ah[0][0],ah[0][1],ah[0][2],ah[0][3], ab);
                ldsm4(ah[1][0],ah[1][1],ah[1][2],ah[1][3], ab + 1280);
                ldsm4(al[0][0],al[0][1],al[0][2],al[0][3], ab + 10240);
                ldsm4(al[1][0],al[1][1],al[1][2],al[1][3], ab + 11520);
                u32 bb0 = bab + (u32)((sub*32 + ka*16) * 2);
                #pragma unroll
                for (int p = 0; p < 4; p++){
                    u32 h0,h1,h2,h3;
                    ldsm4(h0,h1,h2,h3, bb0 + p*4352);
                    #pragma unroll
                    for (int am = 0; am < 2; am++){
                        mma16816(acc[am][2*p],   ah[am], h0, h1);
                        mma16816(acc[am][2*p],   al[am], h0, h1);
                        mma16816(acc[am][2*p+1], ah[am], h2, h3);
                        mma16816(acc[am][2*p+1], al[am], h2, h3);
                    }
                }
            }
        }

        __syncthreads();
        float* s_red = (float*)smem;   // 64 x 132 floats = 33,792 B < EO_B_HI
        #pragma unroll
        for (int phase = 0; phase < 2; phase++){
            if ((warp_m >> 1) == phase){
                #pragma unroll
                for (int am = 0; am < 2; am++)
                    #pragma unroll
                    for (int na = 0; na < 8; na++){
                        int ml = (warp_m & 1)*32 + am*16 + (lane >> 2);
                        int m0 = phase*64 + ml;
                        int n0 = warp_n*64 + na*8 + (lane & 3)*2;
                        float4 c = acc[am][na];
                        float bx = bias[n0], by = bias[n0+1];
                        float v0 = c.x + bx, v1 = c.y + by;
                        float v2 = c.z + bx, v3 = c.w + by;
                        s_red[ml*132 + n0]       = v0;
                        s_red[ml*132 + n0+1]     = v1;
                        s_red[(ml+8)*132 + n0]   = v2;
                        s_red[(ml+8)*132 + n0+1] = v3;
                        int r0 = base + m0;
                        if (r0 < rows)     *(float2*)&out[(size_t)r0*HH + n0]     = make_float2(v0,v1);
                        if (r0 + 8 < rows) *(float2*)&out[(size_t)(r0+8)*HH + n0] = make_float2(v2,v3);
                    }
            }
            __syncthreads();
            int nval = min(64, rows - base - phase*64);
            if (tid < 128 && nval > 0){
                float s = 0.f, s2 = 0.f;
                for (int rr = 0; rr < nval; rr++){
                    float v = s_red[rr*132 + tid];
                    s += v; s2 += v*v;
                }
                atomicAdd(&g_sum[tid], s);
                atomicAdd(&g_sumsq[tid], s2);
            }
            __syncthreads();
        }
    }

    // fused BN2 fin
    __threadfence();
    __shared__ int s_rank;
    if (tid == 0) s_rank = atomicAdd(&g_tick, 1);
    __syncthreads();
    if (s_rank == (int)gridDim.x - 1){
        bn_fin_dev(tid, fg, fb);
        __threadfence();
        if (tid == 0) g_tick = 0;
    }
}

// ---------------- ONE-SHOT weight image prep (all 43 chunks) ----------------
__global__ void k_prepB_all(const float* __restrict__ embW2,
                            const float* __restrict__ m1W,
                            const float* __restrict__ m2W,
                            const float* __restrict__ u1W,
                            const float* __restrict__ u2W,
                            char* __restrict__ img){
    int idx = blockIdx.x*blockDim.x + threadIdx.x;
    if (idx >= NCHUNK_TOT * 16384) return;
    int c = idx >> 14;
    int rem = idx & 16383;
    int n = rem & 127;
    int kcol = rem >> 7;

    const float* W;
    if (c == 0){
        W = embW2;
    } else {
        int l = (c - 1) / 7;
        int r = (c - 1) % 7;
        if      (r == 0) W = m1W + (size_t)l*260*128;
        else if (r == 1) W = m1W + (size_t)l*260*128 + 128*128;
        else if (r == 2) W = m2W + (size_t)l*128*128;
        else if (r == 3) W = u1W + (size_t)l*257*128;
        else if (r == 4) W = u1W + (size_t)l*257*128 + 128*128;
        else if (r == 6) W = u2W + (size_t)l*128*128;
        else return;
    }
    float w = W[(size_t)kcol*128 + n];
    ((__half*)(img + (size_t)c*65536))[n*128 + kcol] = __float2half_rn(w);
}

// ---------------- small kernels ----------------
__global__ void k_pre(const float* __restrict__ pos){
    int n = blockIdx.x*blockDim.x + threadIdx.x;
    if (n < NN){ g_var[n] = pos[n*3+0]; g_cnt[n] = 0; }
}
__global__ void k_hist(const int* __restrict__ dst){
    int e = blockIdx.x*blockDim.x + threadIdx.x;
    if (e < NE) atomicAdd(&g_cnt[dst[e]], 1);
}
#define SBK 512
__global__ __launch_bounds__(SBK)
void k_scanA(){
    __shared__ int sd[SBK];
    int b = blockIdx.x, t = threadIdx.x;
    int i = b*SBK + t;
    int c = (i < NN) ? g_cnt[i] : 0;
    sd[t] = c; __syncthreads();
    for (int off = 1; off < SBK; off <<= 1){
        int add = (t >= off) ? sd[t-off] : 0;
        __syncthreads();
        sd[t] += add;
        __syncthreads();
    }
    if (i < NN) g_woff[i] = sd[t] - c;
    if (t == SBK-1) g_bsum[b] = sd[t];
}
__global__ void k_scanB(int nb){
    __shared__ int s[128];
    int t = threadIdx.x;
    s[t] = (t < nb) ? g_bsum[t] : 0;
    __syncthreads();
    if (t == 0){
        int run = 0;
        for (int i = 0; i < nb; i++){ int c = s[i]; s[i] = run; run += c; }
    }
    __syncthreads();
    if (t < nb) g_bsum[t] = s[t];
}
__global__ void k_scanC(){
    int i = blockIdx.x*blockDim.x + threadIdx.x;
    if (i < NN){
        g_woff[i] += g_bsum[i / SBK];
        g_invdeg[i] = 1.f / fmaxf((float)g_cnt[i], 1.f);
    }
}
__global__ void k_scatter(const float* __restrict__ u, const float* __restrict__ pos,
                          const int* __restrict__ src, const int* __restrict__ dst){
    int e = blockIdx.x*blockDim.x + threadIdx.x;
    if (e < NE){
        int s = src[e], d = dst[e];
        int p = atomicAdd(&g_woff[d], 1);
        g_sdst[p] = d;
        g_ssrc[p] = s;
        g_tl[p] = make_float4(u[d]-u[s],
                              pos[d*3+1]-pos[s*3+1],
                              pos[d*3+2]-pos[s*3+2],
                              pos[d*3+0]);
    }
}
__global__ void k_h0(const float* __restrict__ u, const float* __restrict__ pos,
                     const float* __restrict__ W1, const float* __restrict__ b1){
    int idx = blockIdx.x*blockDim.x + threadIdx.x;
    if (idx < NN*HH){
        int n = idx >> 7, j = idx & 127;
        g_hn[idx] = u[n]       * W1[j]
                  + pos[n*3+1] * W1[128+j]
                  + pos[n*3+2] * W1[256+j]
                  + pos[n*3+0] * W1[384+j]
                  + b1[j];
    }
}
// stats of raw h0 + fused BN1 fin (last block)
__global__ void k_bn_stats(const float* __restrict__ x,
                           const float* __restrict__ fg, const float* __restrict__ fb){
    int j = threadIdx.x;
    int r0 = blockIdx.x * 256;
    int rend = min(r0 + 256, NN);
    float s = 0.f, s2 = 0.f;
    for (int r = r0; r < rend; r++){
        float v = x[(size_t)r*HH + j];
        s += v; s2 += v*v;
    }
    atomicAdd(&g_sum[j], s);
    atomicAdd(&g_sumsq[j], s2);
    __threadfence();
    __shared__ int s_rank;
    if (j == 0) s_rank = atomicAdd(&g_tick, 1);
    __syncthreads();
    if (s_rank == (int)gridDim.x - 1){
        bn_fin_dev(j, fg, fb);
        __threadfence();
        if (j == 0) g_tick = 0;
    }
}

// ---------------- CNN head ----------------
__global__ __launch_bounds__(64)
void k_cnn(const float* __restrict__ c1W, const float* __restrict__ c1b,
           const float* __restrict__ c2W, const float* __restrict__ c2b,
           const float* __restrict__ c3W, const float* __restrict__ c3b,
           float* __restrict__ out){
    __shared__ float sx[64][129];
    __shared__ float w1[64], w2[384], w3[64], b1[4], b2[8], b3[1];
    int tid = threadIdx.x;
    int base = blockIdx.x * 64;

    w1[tid] = c1W[tid];
    w3[tid] = c3W[tid];
    for (int i = tid; i < 384; i += 64) w2[i] = c2W[i];
    if (tid < 4) b1[tid] = c1b[tid];
    if (tid < 8) b2[tid] = c2b[tid];
    if (tid == 0) b3[0] = c3b[0];

    float a0 = g_ba[tid],    c0 = g_bc[tid];
    float a1_ = g_ba[tid+64], c1_ = g_bc[tid+64];
    for (int r = 0; r < 64; r++){
        int row = base + r; int rr = row < NN ? row : NN-1;
        sx[r][tid]    = a0 * g_hn[(size_t)rr*HH + tid]      + c0;
        sx[r][tid+64] = a1_* g_hn[(size_t)rr*HH + tid + 64] + c1_;
    }
    __syncthreads();

    int node = base + tid;
    if (node >= NN) return;

    float o1[4][38];
    #pragma unroll
    for (int c = 0; c < 4; c++)
        for (int p = 0; p < 38; p++){
            float s = b1[c];
            #pragma unroll
            for (int k = 0; k < 16; k++) s += sx[tid][3*p+k] * w1[c*16+k];
            o1[c][p] = fmaxf(s, 0.f);
        }
    float o2[8][9];
    for (int o = 0; o < 8; o++)
        for (int q = 0; q < 9; q++){
            float s = b2[o];
            for (int c = 0; c < 4; c++)
                #pragma unroll
                for (int k = 0; k < 12; k++) s += o1[c][3*q+k] * w2[(o*4+c)*12+k];
            o2[o][q] = fmaxf(s, 0.f);
        }
    float s = b3[0];
    #pragma unroll
    for (int o = 0; o < 8; o++)
        #pragma unroll
        for (int k = 0; k < 8; k++) s += o2[o][k] * w3[o*8+k];

    out[node] = 0.001f * s;
}

// ---------------- launch ----------------
extern "C" void kernel_launch(void* const* d_in, const int* in_sizes, int n_in,
                              void* d_out, int out_size)
{
    const float* u      = (const float*)d_in[0];
    const float* pos    = (const float*)d_in[1];
    const int*   ei     = (const int*)  d_in[2];
    const int*   src    = ei;
    const int*   dst    = ei + NE;
    const float* emb_W1 = (const float*)d_in[3];
    const float* emb_b1 = (const float*)d_in[4];
    const float* emb_g1 = (const float*)d_in[5];
    const float* emb_be1= (const float*)d_in[6];
    const float* emb_W2 = (const float*)d_in[7];
    const float* emb_b2 = (const float*)d_in[8];
    const float* emb_g2 = (const float*)d_in[9];
    const float* emb_be2= (const float*)d_in[10];
    const float* m1W    = (const float*)d_in[11];
    const float* m1b    = (const float*)d_in[12];
    const float* m2W    = (const float*)d_in[13];
    const float* m2b    = (const float*)d_in[14];
    const float* u1W    = (const float*)d_in[15];
    const float* u1b    = (const float*)d_in[16];
    const float* u2W    = (const float*)d_in[17];
    const float* u2b    = (const float*)d_in[18];
    const float* bng    = (const float*)d_in[19];
    const float* bnb    = (const float*)d_in[20];
    const float* c1W    = (const float*)d_in[21];
    const float* c1b    = (const float*)d_in[22];
    const float* c2W    = (const float*)d_in[23];
    const float* c2b    = (const float*)d_in[24];
    const float* c3W    = (const float*)d_in[25];
    const float* c3b    = (const float*)d_in[26];
    float* out = (float*)d_out;

    float *p_hn, *p_up, *p_agg, *p_Pd, *p_Ps;
    char *p_img;
    cudaGetSymbolAddress((void**)&p_hn,   g_hn);
    cudaGetSymbolAddress((void**)&p_up,   g_up);
    cudaGetSymbolAddress((void**)&p_agg,  g_agg);
    cudaGetSymbolAddress((void**)&p_Pd,   g_Pd);
    cudaGetSymbolAddress((void**)&p_Ps,   g_Ps);
    cudaGetSymbolAddress((void**)&p_img,  g_Bimg);

    cudaFuncSetAttribute(gemm_edge, cudaFuncAttributeMaxDynamicSharedMemorySize, FO::TOT);
    cudaFuncSetAttribute(gemm_pdps, cudaFuncAttributeMaxDynamicSharedMemorySize, PO::TOT);
    cudaFuncSetAttribute(gemm_emb,  cudaFuncAttributeMaxDynamicSharedMemorySize, EO_SMEM);
    cudaFuncSetAttribute(gemm_u1,   cudaFuncAttributeMaxDynamicSharedMemorySize, U1O::TOT);
    cudaFuncSetAttribute(gemm_u2,   cudaFuncAttributeMaxDynamicSharedMemorySize, U2O::TOT);

    const int NB  = (NN + SBK - 1) / SBK;
    const int GO  = 296;   // 2-CTA/SM grids
    const int GF  = 304;
    const int GP  = 152;   // pdps (1 CTA/SM)

    auto chunk = [&](int idx) -> char* { return p_img + (size_t)idx * 65536; };

    // ---- prep ALL weight images in one launch ----
    k_prepB_all<<<(NCHUNK_TOT*16384+255)/256,256>>>(emb_W2, m1W, m2W, u1W, u2W, p_img);

    // ---- preprocessing ----
    k_pre<<<(NN+255)/256,256>>>(pos);
    k_hist<<<(NE+255)/256,256>>>(dst);
    k_scanA<<<NB,SBK>>>();
    k_scanB<<<1,128>>>(NB);
    k_scanC<<<(NN+255)/256,256>>>();
    k_scatter<<<(NE+255)/256,256>>>(u, pos, src, dst);

    // ---- embedding (BN1 fin fused into stats; BN2 fin fused into emb GEMM) ----
    k_h0<<<(NN*HH+255)/256,256>>>(u, pos, emb_W1, emb_b1);
    k_bn_stats<<<(NN+255)/256,128>>>(p_hn, emb_g1, emb_be1);
    gemm_emb<<<GO,256,EO_SMEM>>>(p_hn, chunk(0), emb_b2, p_hn, NN, emb_g2, emb_be2);

    // ---- message-passing layers ----
    for (int i = 0; i < LL; i++){
        const float* Wt = m1W + (size_t)i*260*128 + 256*128;
        const float* wv = u1W + (size_t)i*257*128 + 256*128;   // rank-1 var row of u1_W
        gemm_pdps<<<GP,256,PO::TOT>>>(chunk(1+i*7+0), chunk(1+i*7+1),
                                      m1b + i*128, p_Pd, p_Ps, NN);
        gemm_edge<<<GF,256,FO::TOT>>>(chunk(1+i*7+2), m2b + i*128, p_agg, Wt, NE);
        gemm_u1<<<GO,256,U1O::TOT>>>(chunk(1+i*7+3), u1b + i*128, wv, p_up, NN);
        gemm_u2<<<GO,256,U2O::TOT>>>(p_up, chunk(1+i*7+6), u2b + i*128, p_hn, NN,
                                     bng + i*128, bnb + i*128);
    }

    // ---- CNN head ----
    k_cnn<<<(NN+63)/64,64>>>(c1W, c1b, c2W, c2b, c3W, c3b, out);
}